// round 1
// baseline (speedup 1.0000x reference)
#include <cuda_runtime.h>
#include <math_constants.h>
#include <math.h>

// Problem constants
#define B_  8
#define L_  1024
#define S_  1024
#define D_  256
#define V_  256
#define H_  8
#define HD_ 32
#define VD_ 32

#define N_TOK (B_*L_)          // 8192
#define SCALE_F 0.17677669529663687f  // 32^-0.5

// ---------------- scratch (static device arrays: allocation-free) ----------
__device__ float g_qs[B_*L_*D_];
__device__ float g_qo[B_*L_*D_];
__device__ float g_ks[B_*S_*D_];
__device__ float g_ko[B_*S_*D_];
__device__ float g_vh[B_*S_*D_];
__device__ float g_ctx[B_*L_*V_];

// ---------------------------------------------------------------------------
// GEMM: C[M][N] = scale * (A[M][K] @ Bw[N][K]^T) + (bias ? bias[n] : 0)
// BM=128, BN=64, BK=16, 256 threads, 8x4 register tile.
// ---------------------------------------------------------------------------
__global__ __launch_bounds__(256)
void gemm_nt(const float* __restrict__ A, const float* __restrict__ Bw,
             float* __restrict__ C, int M, int N, int K,
             float scale, const float* __restrict__ bias)
{
    const int BM = 128, BN = 64, BK = 16;
    __shared__ __align__(16) float As[BK][BM + 4];
    __shared__ __align__(16) float Bs[BK][BN + 4];

    int t  = threadIdx.x;
    int m0 = blockIdx.y * BM;
    int n0 = blockIdx.x * BN;
    int tx = t & 15;        // 0..15 -> n
    int ty = t >> 4;        // 0..15 -> m

    float acc[8][4];
#pragma unroll
    for (int i = 0; i < 8; i++)
#pragma unroll
        for (int j = 0; j < 4; j++) acc[i][j] = 0.f;

    for (int k0 = 0; k0 < K; k0 += BK) {
        // Load A tile (128x16) as float4, store transposed
#pragma unroll
        for (int i = 0; i < 2; i++) {
            int f  = t + i * 256;            // 0..511
            int r  = f >> 2;                 // 0..127
            int c4 = (f & 3) * 4;            // 0,4,8,12
            float4 vv = *reinterpret_cast<const float4*>(
                &A[(size_t)(m0 + r) * K + k0 + c4]);
            As[c4 + 0][r] = vv.x;
            As[c4 + 1][r] = vv.y;
            As[c4 + 2][r] = vv.z;
            As[c4 + 3][r] = vv.w;
        }
        // Load B tile (64x16)
        {
            int r  = t >> 2;                 // 0..63
            int c4 = (t & 3) * 4;
            float4 vv = *reinterpret_cast<const float4*>(
                &Bw[(size_t)(n0 + r) * K + k0 + c4]);
            Bs[c4 + 0][r] = vv.x;
            Bs[c4 + 1][r] = vv.y;
            Bs[c4 + 2][r] = vv.z;
            Bs[c4 + 3][r] = vv.w;
        }
        __syncthreads();

#pragma unroll
        for (int k = 0; k < BK; k++) {
            float4 a0 = *reinterpret_cast<const float4*>(&As[k][ty * 8]);
            float4 a1 = *reinterpret_cast<const float4*>(&As[k][ty * 8 + 4]);
            float4 b0 = *reinterpret_cast<const float4*>(&Bs[k][tx * 4]);
            float a[8] = {a0.x, a0.y, a0.z, a0.w, a1.x, a1.y, a1.z, a1.w};
            float bb[4] = {b0.x, b0.y, b0.z, b0.w};
#pragma unroll
            for (int i = 0; i < 8; i++)
#pragma unroll
                for (int j = 0; j < 4; j++) acc[i][j] += a[i] * bb[j];
        }
        __syncthreads();
    }

    // Epilogue
    float bv[4] = {0.f, 0.f, 0.f, 0.f};
    if (bias) {
#pragma unroll
        for (int j = 0; j < 4; j++) bv[j] = bias[n0 + tx * 4 + j];
    }
#pragma unroll
    for (int i = 0; i < 8; i++) {
        int row = m0 + ty * 8 + i;
        float4 o;
        o.x = acc[i][0] * scale + bv[0];
        o.y = acc[i][1] * scale + bv[1];
        o.z = acc[i][2] * scale + bv[2];
        o.w = acc[i][3] * scale + bv[3];
        *reinterpret_cast<float4*>(&C[(size_t)row * N + n0 + tx * 4]) = o;
    }
}

// ---------------------------------------------------------------------------
// Attention kernel: one block per (b, 16-row l-tile). Loops all 8 heads,
// keeps the 16x1024 score strip + head-summed prob strip in smem.
// ---------------------------------------------------------------------------
// smem layout (floats):
//   score : 16*1024          = 16384
//   asum  : 16*1024          = 16384
//   kst   : 128*33           = 4224   (aliased by vt in PV phase)
//   kot   : 128*33           = 4224
//   qss   : 16*32            = 512
//   qos   : 16*32            = 512
//   qid_s : 16 (int)
//   kid_s : 1024 (int)
#define ATTN_SMEM_FLOATS (16384 + 16384 + 4224 + 4224 + 512 + 512 + 16 + 1024)
#define ATTN_SMEM_BYTES  (ATTN_SMEM_FLOATS * 4)

__global__ __launch_bounds__(256)
void attn_kernel(const float* __restrict__ mask,
                 const int* __restrict__ qid,
                 const int* __restrict__ kid,
                 float* __restrict__ attn_out)
{
    extern __shared__ float sm[];
    float* score = sm;                       // [16][1024]
    float* asum  = sm + 16 * 1024;           // [16][1024]
    float* kst   = sm + 32768;               // [128][33]
    float* kot   = kst + 4224;               // [128][33]
    float* vt    = kst;                      // alias (PV phase)
    float* qss   = sm + 32768 + 2 * 4224;    // [16][32]
    float* qos   = qss + 512;                // [16][32]
    int*   qid_s = (int*)(qos + 512);        // [16]
    int*   kid_s = qid_s + 16;               // [1024]

    int b    = blockIdx.y;
    int l0   = blockIdx.x * 16;
    int t    = threadIdx.x;
    int lane = t & 31;
    int warp = t >> 5;

    for (int i = t; i < S_; i += 256) kid_s[i] = kid[b * S_ + i];
    if (t < 16) qid_s[t] = qid[b * L_ + l0 + t];
    for (int i = t; i < 16 * 1024; i += 256) asum[i] = 0.f;

    for (int h = 0; h < H_; h++) {
        // load q strips for this head
        for (int i = t; i < 512; i += 256) {
            int l = i >> 5, d = i & 31;
            size_t base = ((size_t)(b * L_ + l0 + l)) * D_ + h * HD_ + d;
            qss[i] = g_qs[base];
            qos[i] = g_qo[base];
        }
        __syncthreads();

        // ---- score phase: score[16][1024] ----
        for (int st = 0; st < 8; st++) {
            int s0 = st * 128;
            for (int i = t; i < 4096; i += 256) {
                int r = i >> 5, c = i & 31;
                size_t base = ((size_t)(b * S_ + s0 + r)) * D_ + h * HD_ + c;
                kst[r * 33 + c] = g_ks[base];
                kot[r * 33 + c] = g_ko[base];
            }
            __syncthreads();

            int la = warp * 2;    // this warp's two l rows: la, la+1
            float aS0[4] = {0, 0, 0, 0}, aS1[4] = {0, 0, 0, 0};
            float aO0[4] = {0, 0, 0, 0}, aO1[4] = {0, 0, 0, 0};
#pragma unroll
            for (int d = 0; d < 32; d++) {
                float q0s = qss[la * 32 + d];
                float q1s = qss[la * 32 + 32 + d];
                float q0o = qos[la * 32 + d];
                float q1o = qos[la * 32 + 32 + d];
#pragma unroll
                for (int j = 0; j < 4; j++) {
                    int ss = lane + 32 * j;
                    float ksv = kst[ss * 33 + d];
                    float kov = kot[ss * 33 + d];
                    aS0[j] += q0s * ksv;
                    aS1[j] += q1s * ksv;
                    aO0[j] += q0o * kov;
                    aO1[j] += q1o * kov;
                }
            }
#pragma unroll
            for (int j = 0; j < 4; j++) {
                int ss = lane + 32 * j;
                int s  = s0 + ss;
                {
                    int l = la;
                    float sc = (qid_s[l] == kid_s[s]) ? aS0[j] : aO0[j];
                    sc += mask[((size_t)(b * L_) + l0 + l) * S_ + s];
                    score[l * 1024 + s] = sc;
                }
                {
                    int l = la + 1;
                    float sc = (qid_s[l] == kid_s[s]) ? aS1[j] : aO1[j];
                    sc += mask[((size_t)(b * L_) + l0 + l) * S_ + s];
                    score[l * 1024 + s] = sc;
                }
            }
            __syncthreads();
        }

        // ---- softmax (warp w owns rows w and w+8) ----
#pragma unroll
        for (int rr = 0; rr < 2; rr++) {
            int r = warp + rr * 8;
            float* row = score + r * 1024;
            float m = -CUDART_INF_F;
            for (int i = lane; i < 1024; i += 32) m = fmaxf(m, row[i]);
#pragma unroll
            for (int o = 16; o > 0; o >>= 1)
                m = fmaxf(m, __shfl_xor_sync(0xffffffffu, m, o));
            float sum = 0.f;
            for (int i = lane; i < 1024; i += 32) {
                float e = __expf(row[i] - m);
                row[i] = e;
                sum += e;
            }
#pragma unroll
            for (int o = 16; o > 0; o >>= 1)
                sum += __shfl_xor_sync(0xffffffffu, sum, o);
            float inv = 1.0f / sum;
            float* ar = asum + r * 1024;
            for (int i = lane; i < 1024; i += 32) {
                float p = row[i] * inv;
                row[i] = p;
                ar[i] += p;
            }
        }
        __syncthreads();

        // ---- PV phase: ctx[16][32] = p[16][1024] @ v[1024][32] ----
        int d  = lane;
        int lg = warp;   // rows lg and lg+8
        float acc0 = 0.f, acc1 = 0.f;
        for (int st = 0; st < 8; st++) {
            for (int i = t; i < 4096; i += 256) {
                int r = i >> 5, c = i & 31;
                vt[r * 33 + c] =
                    g_vh[((size_t)(b * S_ + st * 128 + r)) * D_ + h * HD_ + c];
            }
            __syncthreads();
            const float* p0 = score + lg * 1024 + st * 128;
            const float* p1 = score + (lg + 8) * 1024 + st * 128;
#pragma unroll 4
            for (int ss = 0; ss < 128; ss++) {
                float vv = vt[ss * 33 + d];
                acc0 += p0[ss] * vv;
                acc1 += p1[ss] * vv;
            }
            __syncthreads();
        }
        g_ctx[((size_t)(b * L_ + l0 + lg)) * V_ + h * HD_ + d]     = acc0;
        g_ctx[((size_t)(b * L_ + l0 + lg + 8)) * V_ + h * HD_ + d] = acc1;
        // next-head q-load is followed by a __syncthreads before use; PV's
        // final sync already ordered all strip reads.
    }

    __syncthreads();
    for (int i = t; i < 16 * 1024; i += 256) {
        int l = i >> 10, s = i & 1023;
        attn_out[((size_t)(b * L_) + l0 + l) * S_ + s] = asum[i] * 0.125f;
    }
}

// ---------------------------------------------------------------------------
extern "C" void kernel_launch(void* const* d_in, const int* in_sizes, int n_in,
                              void* d_out, int out_size)
{
    const float* q    = (const float*)d_in[0];
    const float* k    = (const float*)d_in[1];
    const float* v    = (const float*)d_in[2];
    const int*   qid  = (const int*)d_in[3];
    const int*   kid  = (const int*)d_in[4];
    const float* mask = (const float*)d_in[5];
    const float* wqs  = (const float*)d_in[6];
    const float* wqo  = (const float*)d_in[7];
    const float* wks  = (const float*)d_in[8];
    const float* wko  = (const float*)d_in[9];
    const float* wv   = (const float*)d_in[10];
    const float* fcw  = (const float*)d_in[11];
    const float* fcb  = (const float*)d_in[12];

    float* out      = (float*)d_out;
    float* attn_out = out + (size_t)B_ * L_ * V_;   // tuple order: (out, attn)

    void *p_qs, *p_qo, *p_ks, *p_ko, *p_vh, *p_ctx;
    cudaGetSymbolAddress(&p_qs,  g_qs);
    cudaGetSymbolAddress(&p_qo,  g_qo);
    cudaGetSymbolAddress(&p_ks,  g_ks);
    cudaGetSymbolAddress(&p_ko,  g_ko);
    cudaGetSymbolAddress(&p_vh,  g_vh);
    cudaGetSymbolAddress(&p_ctx, g_ctx);

    cudaFuncSetAttribute(attn_kernel,
                         cudaFuncAttributeMaxDynamicSharedMemorySize,
                         ATTN_SMEM_BYTES);

    dim3 ggrid(V_ / 64, N_TOK / 128);   // (4, 64)

    // Projections
    gemm_nt<<<ggrid, 256>>>(q, wqs, (float*)p_qs, N_TOK, D_, D_, SCALE_F, nullptr);
    gemm_nt<<<ggrid, 256>>>(q, wqo, (float*)p_qo, N_TOK, D_, D_, SCALE_F, nullptr);
    gemm_nt<<<ggrid, 256>>>(k, wks, (float*)p_ks, N_TOK, D_, D_, 1.0f, nullptr);
    gemm_nt<<<ggrid, 256>>>(k, wko, (float*)p_ko, N_TOK, D_, D_, 1.0f, nullptr);
    gemm_nt<<<ggrid, 256>>>(v, wv,  (float*)p_vh, N_TOK, D_, D_, 1.0f, nullptr);

    // Attention
    dim3 agrid(L_ / 16, B_);   // (64, 8)
    attn_kernel<<<agrid, 256, ATTN_SMEM_BYTES>>>(mask, qid, kid, attn_out);

    // FC
    gemm_nt<<<ggrid, 256>>>((const float*)p_ctx, fcw, out, N_TOK, V_, V_, 1.0f, fcb);
}

// round 2
// speedup vs baseline: 1.8121x; 1.8121x over previous
#include <cuda_runtime.h>
#include <math_constants.h>

#define B_  8
#define L_  1024
#define S_  1024
#define D_  256
#define V_  256
#define H_  8

#define N_TOK (B_*L_)
#define SCALE_F 0.17677669529663687f

// ---------------- scratch (static device arrays: allocation-free) ----------
__device__ float g_qs[N_TOK*D_];
__device__ float g_qo[N_TOK*D_];
__device__ float g_ks[N_TOK*D_];
__device__ float g_ko[N_TOK*D_];
__device__ float g_vh[N_TOK*D_];
__device__ float g_ctx[N_TOK*V_];

// ---------------- fast exp on FMA pipe (rel err ~2e-6) ---------------------
__device__ __forceinline__ float fexp(float x)
{
    float t = fmaxf(x * 1.4426950408889634f, -125.0f);
    float r = rintf(t);
    float f = t - r;
    float p = 1.3333558146428443e-3f;
    p = fmaf(p, f, 9.6181291076284772e-3f);
    p = fmaf(p, f, 5.5504108664821580e-2f);
    p = fmaf(p, f, 2.4022650695910071e-1f);
    p = fmaf(p, f, 6.9314718055994531e-1f);
    p = fmaf(p, f, 1.0f);
    return __int_as_float(__float_as_int(p) + (((int)r) << 23));
}

// ---------------------------------------------------------------------------
// GEMM body: C[M][N] = scale * (A[M][K] @ Bw[N][K]^T) + (bias ? bias[n] : 0)
// BM=128, BN=64, BK=16, 256 threads, 8x4 register tile. (proven in R1)
// ---------------------------------------------------------------------------
__device__ __forceinline__ void gemm_body(
    const float* __restrict__ A, const float* __restrict__ Bw,
    float* __restrict__ C, int N, int K,
    float scale, const float* __restrict__ bias)
{
    const int BM = 128, BN = 64, BK = 16;
    __shared__ __align__(16) float As[BK][BM + 4];
    __shared__ __align__(16) float Bs[BK][BN + 4];

    int t  = threadIdx.x;
    int m0 = blockIdx.y * BM;
    int n0 = blockIdx.x * BN;
    int tx = t & 15;
    int ty = t >> 4;

    float acc[8][4];
#pragma unroll
    for (int i = 0; i < 8; i++)
#pragma unroll
        for (int j = 0; j < 4; j++) acc[i][j] = 0.f;

    for (int k0 = 0; k0 < K; k0 += BK) {
#pragma unroll
        for (int i = 0; i < 2; i++) {
            int f  = t + i * 256;
            int r  = f >> 2;
            int c4 = (f & 3) * 4;
            float4 vv = *reinterpret_cast<const float4*>(
                &A[(size_t)(m0 + r) * K + k0 + c4]);
            As[c4 + 0][r] = vv.x;
            As[c4 + 1][r] = vv.y;
            As[c4 + 2][r] = vv.z;
            As[c4 + 3][r] = vv.w;
        }
        {
            int r  = t >> 2;
            int c4 = (t & 3) * 4;
            float4 vv = *reinterpret_cast<const float4*>(
                &Bw[(size_t)(n0 + r) * K + k0 + c4]);
            Bs[c4 + 0][r] = vv.x;
            Bs[c4 + 1][r] = vv.y;
            Bs[c4 + 2][r] = vv.z;
            Bs[c4 + 3][r] = vv.w;
        }
        __syncthreads();

#pragma unroll
        for (int k = 0; k < BK; k++) {
            float4 a0 = *reinterpret_cast<const float4*>(&As[k][ty * 8]);
            float4 a1 = *reinterpret_cast<const float4*>(&As[k][ty * 8 + 4]);
            float4 b0 = *reinterpret_cast<const float4*>(&Bs[k][tx * 4]);
            float a[8] = {a0.x, a0.y, a0.z, a0.w, a1.x, a1.y, a1.z, a1.w};
            float bb[4] = {b0.x, b0.y, b0.z, b0.w};
#pragma unroll
            for (int i = 0; i < 8; i++)
#pragma unroll
                for (int j = 0; j < 4; j++) acc[i][j] += a[i] * bb[j];
        }
        __syncthreads();
    }

    float bv[4] = {0.f, 0.f, 0.f, 0.f};
    if (bias) {
#pragma unroll
        for (int j = 0; j < 4; j++) bv[j] = bias[n0 + tx * 4 + j];
    }
#pragma unroll
    for (int i = 0; i < 8; i++) {
        int row = m0 + ty * 8 + i;
        float4 o;
        o.x = acc[i][0] * scale + bv[0];
        o.y = acc[i][1] * scale + bv[1];
        o.z = acc[i][2] * scale + bv[2];
        o.w = acc[i][3] * scale + bv[3];
        *reinterpret_cast<float4*>(&C[(size_t)row * N + n0 + tx * 4]) = o;
    }
}

// Fused 5-projection launch: blockIdx.z selects (A, W, C, scale)
struct Proj5 {
    const float* A[5];
    const float* W[5];
    float*       C[5];
    float        sc[5];
};

__global__ __launch_bounds__(256)
void proj_kernel(Proj5 p)
{
    int z = blockIdx.z;
    gemm_body(p.A[z], p.W[z], p.C[z], D_, D_, p.sc[z], nullptr);
}

__global__ __launch_bounds__(256)
void fc_kernel(const float* __restrict__ A, const float* __restrict__ W,
               const float* __restrict__ bias, float* __restrict__ C)
{
    gemm_body(A, W, C, V_, V_, 1.0f, bias);
}

// ---------------------------------------------------------------------------
// Attention: block = (b, 16 l-rows), 256 threads, 2 blocks/SM.
// smem floats: score 16384 | kst 4608 | kot 4608 | qss 512 | qos 512
//              inv 16 | qid 16(int) | kid 1024(int)  => 110,720 bytes
// ---------------------------------------------------------------------------
#define AT_SMEM_BYTES ((16384 + 4608 + 4608 + 512 + 512 + 16 + 16 + 1024) * 4)

__global__ __launch_bounds__(256, 2)
void attn_kernel(const float* __restrict__ mask,
                 const int* __restrict__ qid,
                 const int* __restrict__ kid,
                 float* __restrict__ attn_out)
{
    extern __shared__ float sm[];
    float* score = sm;                    // [16][1024]
    float* kst   = sm + 16384;            // [128][36]
    float* kot   = kst + 4608;            // [128][36]
    float* vt    = kst;                   // alias for PV phase
    float* qss   = kot + 4608;            // [16][32]
    float* qos   = qss + 512;             // [16][32]
    float* inv   = qos + 512;             // [16]
    int*   qid_s = (int*)(inv + 16);      // [16]
    int*   kid_s = qid_s + 16;            // [1024]

    const int b    = blockIdx.y;
    const int l0   = blockIdx.x * 16;
    const int t    = threadIdx.x;
    const int lane = t & 31;
    const int w    = t >> 5;
    const int mat  = w & 1;               // 0 = self, 1 = other
    const int rg   = w >> 1;              // rows rg*4 .. rg*4+3 (score phase)
    const int row0 = 2 * w, row1 = 2 * w + 1; // softmax/PV rows

    for (int i = t; i < S_; i += 256) kid_s[i] = kid[b * S_ + i];
    if (t < 16) qid_s[t] = qid[b * L_ + l0 + t];

    float asum[64];
#pragma unroll
    for (int u = 0; u < 64; u++) asum[u] = 0.f;

    for (int h = 0; h < H_; h++) {
        // ---- q strips for this head (both matrices) ----
#pragma unroll
        for (int u = 0; u < 2; u++) {
            int i = t + 256 * u;
            int l = i >> 5, d = i & 31;
            size_t gb = ((size_t)(b * L_ + l0 + l)) * D_ + h * 32 + d;
            qss[i] = g_qs[gb];
            qos[i] = g_qo[gb];
        }

        const float* qsrc = mat ? qos : qss;
        const float* ksm  = mat ? kot : kst;

        // ---- score phase: 8 s-tiles of 128 ----
        for (int st = 0; st < 8; st++) {
            __syncthreads();   // previous tile readers done / q+ids visible
#pragma unroll
            for (int u = 0; u < 8; u++) {
                int f  = t + 256 * u;           // 0..2047 float4 slots
                int mm = f >> 10;
                int r  = (f >> 3) & 127;
                int c4 = (f & 7) * 4;
                const float* src = mm ? g_ko : g_ks;
                float4 x = *reinterpret_cast<const float4*>(
                    &src[((size_t)(b * S_ + st * 128 + r)) * D_ + h * 32 + c4]);
                float* dst = mm ? kot : kst;
                *reinterpret_cast<float4*>(&dst[r * 36 + c4]) = x;
            }
            __syncthreads();

            float acc[4][4];
#pragma unroll
            for (int r = 0; r < 4; r++)
#pragma unroll
                for (int j = 0; j < 4; j++) acc[r][j] = 0.f;

#pragma unroll
            for (int d4 = 0; d4 < 8; d4++) {
                float4 qv[4], kv[4];
#pragma unroll
                for (int r = 0; r < 4; r++)
                    qv[r] = *reinterpret_cast<const float4*>(
                        &qsrc[((rg * 4 + r) << 5) + d4 * 4]);
#pragma unroll
                for (int j = 0; j < 4; j++)
                    kv[j] = *reinterpret_cast<const float4*>(
                        &ksm[(lane + 32 * j) * 36 + d4 * 4]);
#pragma unroll
                for (int r = 0; r < 4; r++)
#pragma unroll
                    for (int j = 0; j < 4; j++) {
                        acc[r][j] = fmaf(qv[r].x, kv[j].x, acc[r][j]);
                        acc[r][j] = fmaf(qv[r].y, kv[j].y, acc[r][j]);
                        acc[r][j] = fmaf(qv[r].z, kv[j].z, acc[r][j]);
                        acc[r][j] = fmaf(qv[r].w, kv[j].w, acc[r][j]);
                    }
            }

            // select + mask + write (self-warp writes where ids match,
            // other-warp writes the complement -> each element once)
#pragma unroll
            for (int r = 0; r < 4; r++) {
                int row = rg * 4 + r;
                int qi  = qid_s[row];
                size_t mbase = ((size_t)(b * L_ + l0 + row)) * S_ + st * 128;
#pragma unroll
                for (int j = 0; j < 4; j++) {
                    int sl = lane + 32 * j;
                    bool same = (qi == kid_s[st * 128 + sl]);
                    if (same == (mat == 0))
                        score[(row << 10) + st * 128 + sl] =
                            acc[r][j] + mask[mbase + sl];
                }
            }
        }
        __syncthreads();

        // ---- softmax (warp w owns rows 2w, 2w+1); keep e-values, fold inv ----
        float rinv0 = 0.f, rinv1 = 0.f;
#pragma unroll
        for (int rr = 0; rr < 2; rr++) {
            int row = 2 * w + rr;
            float4* pr = (float4*)(score + (row << 10));
            float mx = -CUDART_INF_F;
            for (int u = lane; u < 256; u += 32) {
                float4 x = pr[u];
                mx = fmaxf(mx, fmaxf(fmaxf(x.x, x.y), fmaxf(x.z, x.w)));
            }
#pragma unroll
            for (int o = 16; o > 0; o >>= 1)
                mx = fmaxf(mx, __shfl_xor_sync(0xffffffffu, mx, o));
            float s = 0.f;
            for (int u = lane; u < 256; u += 32) {
                float4 x = pr[u];
                x.x = fexp(x.x - mx); x.y = fexp(x.y - mx);
                x.z = fexp(x.z - mx); x.w = fexp(x.w - mx);
                s += (x.x + x.y) + (x.z + x.w);
                pr[u] = x;
            }
#pragma unroll
            for (int o = 16; o > 0; o >>= 1)
                s += __shfl_xor_sync(0xffffffffu, s, o);
            float ri = 1.0f / s;
            if (rr == 0) rinv0 = ri; else rinv1 = ri;
            if (lane == 0) inv[row] = ri;
        }
        __syncthreads();

        // ---- attn-sum accumulation (register-resident; l = u>>2 compile-time)
#pragma unroll
        for (int u = 0; u < 64; u++)
            asum[u] += score[t + 256 * u] * inv[u >> 2];

        // ---- PV: ctx[row][d=lane] = (sum_s e * v) * inv ----
        float a0 = 0.f, a0b = 0.f, a1 = 0.f, a1b = 0.f;
        for (int st = 0; st < 8; st++) {
            if (st) __syncthreads();
#pragma unroll
            for (int u = 0; u < 4; u++) {
                int f  = t + 256 * u;           // 0..1023 float4 slots
                int r  = f >> 3;
                int c4 = (f & 7) * 4;
                float4 x = *reinterpret_cast<const float4*>(
                    &g_vh[((size_t)(b * S_ + st * 128 + r)) * D_ + h * 32 + c4]);
                *reinterpret_cast<float4*>(&vt[r * 36 + c4]) = x;
            }
            __syncthreads();
            const float* e0 = score + (row0 << 10) + st * 128;
            const float* e1 = score + (row1 << 10) + st * 128;
#pragma unroll 8
            for (int qd = 0; qd < 32; qd++) {
                float4 x0 = *reinterpret_cast<const float4*>(&e0[qd * 4]);
                float4 x1 = *reinterpret_cast<const float4*>(&e1[qd * 4]);
                float v0 = vt[(qd * 4 + 0) * 36 + lane];
                float v1 = vt[(qd * 4 + 1) * 36 + lane];
                float v2 = vt[(qd * 4 + 2) * 36 + lane];
                float v3 = vt[(qd * 4 + 3) * 36 + lane];
                a0  = fmaf(x0.x, v0, a0);  a0b = fmaf(x0.y, v1, a0b);
                a0  = fmaf(x0.z, v2, a0);  a0b = fmaf(x0.w, v3, a0b);
                a1  = fmaf(x1.x, v0, a1);  a1b = fmaf(x1.y, v1, a1b);
                a1  = fmaf(x1.z, v2, a1);  a1b = fmaf(x1.w, v3, a1b);
            }
        }
        {
            size_t cb = ((size_t)(b * L_ + l0 + row0)) * V_ + h * 32 + lane;
            g_ctx[cb]      = (a0 + a0b) * rinv0;
            g_ctx[cb + V_] = (a1 + a1b) * rinv1;
        }
        // next head: q-store touches qss/qos only (no readers active);
        // kt overwrite is protected by the score-loop top barrier.
    }

    size_t ob = ((size_t)(b * L_ + l0)) * S_;
#pragma unroll
    for (int u = 0; u < 64; u++)
        attn_out[ob + t + 256 * u] = asum[u] * 0.125f;
}

// ---------------------------------------------------------------------------
extern "C" void kernel_launch(void* const* d_in, const int* in_sizes, int n_in,
                              void* d_out, int out_size)
{
    const float* q    = (const float*)d_in[0];
    const float* k    = (const float*)d_in[1];
    const float* v    = (const float*)d_in[2];
    const int*   qid  = (const int*)d_in[3];
    const int*   kid  = (const int*)d_in[4];
    const float* mask = (const float*)d_in[5];
    const float* wqs  = (const float*)d_in[6];
    const float* wqo  = (const float*)d_in[7];
    const float* wks  = (const float*)d_in[8];
    const float* wko  = (const float*)d_in[9];
    const float* wv   = (const float*)d_in[10];
    const float* fcw  = (const float*)d_in[11];
    const float* fcb  = (const float*)d_in[12];

    float* out      = (float*)d_out;
    float* attn_out = out + (size_t)B_ * L_ * V_;

    void *p_qs, *p_qo, *p_ks, *p_ko, *p_vh, *p_ctx;
    cudaGetSymbolAddress(&p_qs,  g_qs);
    cudaGetSymbolAddress(&p_qo,  g_qo);
    cudaGetSymbolAddress(&p_ks,  g_ks);
    cudaGetSymbolAddress(&p_ko,  g_ko);
    cudaGetSymbolAddress(&p_vh,  g_vh);
    cudaGetSymbolAddress(&p_ctx, g_ctx);

    cudaFuncSetAttribute(attn_kernel,
                         cudaFuncAttributeMaxDynamicSharedMemorySize,
                         AT_SMEM_BYTES);

    Proj5 p;
    p.A[0] = q;  p.W[0] = wqs; p.C[0] = (float*)p_qs; p.sc[0] = SCALE_F;
    p.A[1] = q;  p.W[1] = wqo; p.C[1] = (float*)p_qo; p.sc[1] = SCALE_F;
    p.A[2] = k;  p.W[2] = wks; p.C[2] = (float*)p_ks; p.sc[2] = 1.0f;
    p.A[3] = k;  p.W[3] = wko; p.C[3] = (float*)p_ko; p.sc[3] = 1.0f;
    p.A[4] = v;  p.W[4] = wv;  p.C[4] = (float*)p_vh; p.sc[4] = 1.0f;

    dim3 pgrid(V_ / 64, N_TOK / 128, 5);
    proj_kernel<<<pgrid, 256>>>(p);

    dim3 agrid(L_ / 16, B_);
    attn_kernel<<<agrid, 256, AT_SMEM_BYTES>>>(mask, qid, kid, attn_out);

    dim3 fgrid(V_ / 64, N_TOK / 128);
    fc_kernel<<<fgrid, 256>>>((const float*)p_ctx, fcw, fcb, out);
}

// round 3
// speedup vs baseline: 2.0244x; 1.1172x over previous
#include <cuda_runtime.h>
#include <math_constants.h>

#define B_  8
#define L_  1024
#define S_  1024
#define D_  256
#define V_  256
#define H_  8

#define N_TOK (B_*L_)
#define SCALE_F 0.17677669529663687f

typedef unsigned long long ull;

// ---------------- packed fp32x2 helpers (B300 FFMA2 path) ------------------
__device__ __forceinline__ ull fma2(ull a, ull b, ull c)
{
    ull d;
    asm("fma.rn.f32x2 %0, %1, %2, %3;" : "=l"(d) : "l"(a), "l"(b), "l"(c));
    return d;
}
__device__ __forceinline__ float2 unpack2(ull x)
{
    float2 f;
    f.x = __uint_as_float((unsigned)(x & 0xffffffffull));
    f.y = __uint_as_float((unsigned)(x >> 32));
    return f;
}
__device__ __forceinline__ ull pack2(float lo, float hi)
{
    return (ull)__float_as_uint(lo) | ((ull)__float_as_uint(hi) << 32);
}

// ---------------- scratch (static device arrays: allocation-free) ----------
__device__ float g_qs[N_TOK*D_];
__device__ float g_qo[N_TOK*D_];
__device__ float g_ks[N_TOK*D_];
__device__ float g_ko[N_TOK*D_];
__device__ float g_vh[N_TOK*D_];
__device__ float g_ctx[N_TOK*V_];

// ---------------- fast exp on FMA pipe (rel err ~2e-6) ---------------------
__device__ __forceinline__ float fexp(float x)
{
    float t = fmaxf(x * 1.4426950408889634f, -125.0f);
    float r = rintf(t);
    float f = t - r;
    float p = 1.3333558146428443e-3f;
    p = fmaf(p, f, 9.6181291076284772e-3f);
    p = fmaf(p, f, 5.5504108664821580e-2f);
    p = fmaf(p, f, 2.4022650695910071e-1f);
    p = fmaf(p, f, 6.9314718055994531e-1f);
    p = fmaf(p, f, 1.0f);
    return __int_as_float(__float_as_int(p) + (((int)r) << 23));
}

// ---------------------------------------------------------------------------
// GEMM: C[M][N] = scale*(A[M][K] @ Bw[N][K]^T) + bias.  FFMA2 over k-pairs.
// BM=128, BN=64, BK=16, 256 threads, 8x4 tile (acc in f32x2 pairs).
// ---------------------------------------------------------------------------
__device__ __forceinline__ void gemm_body(
    const float* __restrict__ A, const float* __restrict__ Bw,
    float* __restrict__ C, int N, int K,
    float scale, const float* __restrict__ bias)
{
    __shared__ __align__(16) ull As2[8][130];   // [k2][m]
    __shared__ __align__(16) ull Bs2[8][66];    // [k2][n]

    const int t  = threadIdx.x;
    const int m0 = blockIdx.y * 128;
    const int n0 = blockIdx.x * 64;
    const int tx = t & 15;
    const int ty = t >> 4;

    ull acc[8][4];
#pragma unroll
    for (int i = 0; i < 8; i++)
#pragma unroll
        for (int j = 0; j < 4; j++) acc[i][j] = 0ull;

    // prefetch first tile
    float4 pa[2], pb;
    {
        const int ra0 = t >> 2,      ca = (t & 3) * 4;
        pa[0] = *reinterpret_cast<const float4*>(&A[(size_t)(m0 + ra0) * K + ca]);
        pa[1] = *reinterpret_cast<const float4*>(&A[(size_t)(m0 + ra0 + 64) * K + ca]);
        const int rb = t >> 2,       cb = (t & 3) * 4;
        pb    = *reinterpret_cast<const float4*>(&Bw[(size_t)(n0 + rb) * K + cb]);
    }

    for (int k0 = 0; k0 < K; k0 += 16) {
        // STS prefetched tile
        {
            const int r  = t >> 2;
            const int k2 = (t & 3) * 2;
#pragma unroll
            for (int i = 0; i < 2; i++) {
                const ull* pv = reinterpret_cast<const ull*>(&pa[i]);
                As2[k2][r + 64 * i]     = pv[0];
                As2[k2 + 1][r + 64 * i] = pv[1];
            }
            const ull* qv = reinterpret_cast<const ull*>(&pb);
            Bs2[k2][r]     = qv[0];
            Bs2[k2 + 1][r] = qv[1];
        }
        __syncthreads();

        if (k0 + 16 < K) {
            const int ra0 = t >> 2, ca = k0 + 16 + (t & 3) * 4;
            pa[0] = *reinterpret_cast<const float4*>(&A[(size_t)(m0 + ra0) * K + ca]);
            pa[1] = *reinterpret_cast<const float4*>(&A[(size_t)(m0 + ra0 + 64) * K + ca]);
            pb    = *reinterpret_cast<const float4*>(&Bw[(size_t)(n0 + (t >> 2)) * K + ca]);
        }

#pragma unroll
        for (int k2 = 0; k2 < 8; k2++) {
            ull a2[8], b2[4];
            const ulonglong2* ap = reinterpret_cast<const ulonglong2*>(&As2[k2][ty * 8]);
            const ulonglong2* bp = reinterpret_cast<const ulonglong2*>(&Bs2[k2][tx * 4]);
#pragma unroll
            for (int i = 0; i < 4; i++) { ulonglong2 v = ap[i]; a2[2*i] = v.x; a2[2*i+1] = v.y; }
#pragma unroll
            for (int j = 0; j < 2; j++) { ulonglong2 v = bp[j]; b2[2*j] = v.x; b2[2*j+1] = v.y; }
#pragma unroll
            for (int i = 0; i < 8; i++)
#pragma unroll
                for (int j = 0; j < 4; j++)
                    acc[i][j] = fma2(a2[i], b2[j], acc[i][j]);
        }
        __syncthreads();
    }

    float bv[4] = {0.f, 0.f, 0.f, 0.f};
    if (bias) {
#pragma unroll
        for (int j = 0; j < 4; j++) bv[j] = bias[n0 + tx * 4 + j];
    }
#pragma unroll
    for (int i = 0; i < 8; i++) {
        const int row = m0 + ty * 8 + i;
        float4 o;
        float2 f0 = unpack2(acc[i][0]);
        float2 f1 = unpack2(acc[i][1]);
        float2 f2 = unpack2(acc[i][2]);
        float2 f3 = unpack2(acc[i][3]);
        o.x = (f0.x + f0.y) * scale + bv[0];
        o.y = (f1.x + f1.y) * scale + bv[1];
        o.z = (f2.x + f2.y) * scale + bv[2];
        o.w = (f3.x + f3.y) * scale + bv[3];
        *reinterpret_cast<float4*>(&C[(size_t)row * N + n0 + tx * 4]) = o;
    }
}

struct Proj5 {
    const float* A[5];
    const float* W[5];
    float*       C[5];
    float        sc[5];
};

__global__ __launch_bounds__(256, 2)
void proj_kernel(Proj5 p)
{
    int z = blockIdx.z;
    gemm_body(p.A[z], p.W[z], p.C[z], D_, D_, p.sc[z], nullptr);
}

__global__ __launch_bounds__(256, 2)
void fc_kernel(const float* __restrict__ A, const float* __restrict__ W,
               const float* __restrict__ bias, float* __restrict__ C)
{
    gemm_body(A, W, C, V_, V_, 1.0f, bias);
}

// ---------------------------------------------------------------------------
// Attention: block = (b, 16 l-rows), 256 threads, 2 blocks/SM.
// smem floats: score 16384 | kst 4608 | kot 4608 | qss 512 | qos 512
//              inv 16 | qid 16(int) | kid 1024(int)  => 110,720 bytes
// ---------------------------------------------------------------------------
#define AT_SMEM_BYTES ((16384 + 4608 + 4608 + 512 + 512 + 16 + 16 + 1024) * 4)

__global__ __launch_bounds__(256, 2)
void attn_kernel(const float* __restrict__ mask,
                 const int* __restrict__ qid,
                 const int* __restrict__ kid,
                 float* __restrict__ attn_out)
{
    extern __shared__ float sm[];
    float* score = sm;                    // [16][1024]
    float* kst   = sm + 16384;            // [128][36]
    float* kot   = kst + 4608;            // [128][36]
    float* vtT   = kst;                   // alias: [32][132] in PV phase
    float* qss   = kot + 4608;            // [16][32] (PV: ch0 partials)
    float* qos   = qss + 512;             // [16][32] (PV: ch1 partials)
    float* inv   = qos + 512;             // [16]
    int*   qid_s = (int*)(inv + 16);      // [16]
    int*   kid_s = qid_s + 16;            // [1024]

    const int b    = blockIdx.y;
    const int l0   = blockIdx.x * 16;
    const int t    = threadIdx.x;
    const int lane = t & 31;
    const int w    = t >> 5;

    // score-phase warp tiling: mat (self/other), rh (row half), ch (col half)
    const int mat = w & 1;
    const int rh  = (w >> 1) & 1;
    const int ch  = w >> 2;
    // PV warp tiling: 4 rows per warp, s-half ch
    const int rg4 = (w & 3) * 4;

    for (int i = t; i < S_; i += 256) kid_s[i] = kid[b * S_ + i];
    if (t < 16) qid_s[t] = qid[b * L_ + l0 + t];

    const size_t mrow0 = ((size_t)(b * L_ + l0)) * S_;

    for (int h = 0; h < H_; h++) {
        __syncthreads();   // prior head fully done (combine read qss/qos)

        // ---- q strips for this head ----
#pragma unroll
        for (int u = 0; u < 2; u++) {
            int i = t + 256 * u;
            int l = i >> 5, d = i & 31;
            size_t gb = ((size_t)(b * L_ + l0 + l)) * D_ + h * 32 + d;
            qss[i] = g_qs[gb];
            qos[i] = g_qo[gb];
        }

        const float* qsrc = mat ? qos : qss;
        const float* ksm  = mat ? kot : kst;

        // prefetch k tiles (st=0) into regs
        float4 kreg[8];
#pragma unroll
        for (int u = 0; u < 8; u++) {
            int f = t + 256 * u;
            int r = (f >> 3) & 127, c4 = (f & 7) * 4;
            const float* src = (f >> 10) ? g_ko : g_ks;
            kreg[u] = *reinterpret_cast<const float4*>(
                &src[((size_t)(b * S_ + r)) * D_ + h * 32 + c4]);
        }

        // ================= score phase =================
        for (int st = 0; st < 8; st++) {
            __syncthreads();   // tile buffers free / q visible
            // STS k tiles
#pragma unroll
            for (int u = 0; u < 8; u++) {
                int f = t + 256 * u;
                int r = (f >> 3) & 127, c4 = (f & 7) * 4;
                float* dst = (f >> 10) ? kot : kst;
                *reinterpret_cast<float4*>(&dst[r * 36 + c4]) = kreg[u];
            }
            // prefill score tile with mask
#pragma unroll
            for (int u = 0; u < 2; u++) {
                int f = t + 256 * u;          // 0..511 float4 slots
                int row = f >> 5, c4 = (f & 31) * 4;
                float4 mv = *reinterpret_cast<const float4*>(
                    &mask[mrow0 + (size_t)row * S_ + st * 128 + c4]);
                *reinterpret_cast<float4*>(&score[(row << 10) + st * 128 + c4]) = mv;
            }
            __syncthreads();

            // prefetch next tile
            if (st < 7) {
#pragma unroll
                for (int u = 0; u < 8; u++) {
                    int f = t + 256 * u;
                    int r = (f >> 3) & 127, c4 = (f & 7) * 4;
                    const float* src = (f >> 10) ? g_ko : g_ks;
                    kreg[u] = *reinterpret_cast<const float4*>(
                        &src[((size_t)(b * S_ + (st + 1) * 128 + r)) * D_ + h * 32 + c4]);
                }
            }

            // compute: 8 rows x 64 cols per warp, FFMA2 over d-pairs
            ull acc2[8][2];
#pragma unroll
            for (int r = 0; r < 8; r++) { acc2[r][0] = 0ull; acc2[r][1] = 0ull; }

#pragma unroll
            for (int d4 = 0; d4 < 8; d4++) {
                ull kv[2][2];
#pragma unroll
                for (int j = 0; j < 2; j++) {
                    float4 kf = *reinterpret_cast<const float4*>(
                        &ksm[(ch * 64 + lane + 32 * j) * 36 + d4 * 4]);
                    const ull* kp = reinterpret_cast<const ull*>(&kf);
                    kv[j][0] = kp[0]; kv[j][1] = kp[1];
                }
#pragma unroll
                for (int r = 0; r < 8; r++) {
                    float4 qf = *reinterpret_cast<const float4*>(
                        &qsrc[((rh * 8 + r) << 5) + d4 * 4]);
                    const ull* qp = reinterpret_cast<const ull*>(&qf);
#pragma unroll
                    for (int j = 0; j < 2; j++) {
                        acc2[r][j] = fma2(qp[0], kv[j][0], acc2[r][j]);
                        acc2[r][j] = fma2(qp[1], kv[j][1], acc2[r][j]);
                    }
                }
            }

            // select + add prefilled mask + write (predicated, disjoint)
            int kid0 = kid_s[st * 128 + ch * 64 + lane];
            int kid1 = kid_s[st * 128 + ch * 64 + lane + 32];
#pragma unroll
            for (int r = 0; r < 8; r++) {
                int row = rh * 8 + r;
                int qi  = qid_s[row];
#pragma unroll
                for (int j = 0; j < 2; j++) {
                    int sl = st * 128 + ch * 64 + lane + 32 * j;
                    bool same = (qi == (j ? kid1 : kid0));
                    if (same == (mat == 0)) {
                        float2 f = unpack2(acc2[r][j]);
                        int idx = (row << 10) + sl;
                        score[idx] = (f.x + f.y) + score[idx];
                    }
                }
            }
        }
        __syncthreads();

        // ================= softmax (warp w owns rows 2w, 2w+1) ==============
#pragma unroll
        for (int rr = 0; rr < 2; rr++) {
            int row = 2 * w + rr;
            float4* pr = (float4*)(score + (row << 10));
            float mx = -CUDART_INF_F;
            for (int u = lane; u < 256; u += 32) {
                float4 x = pr[u];
                mx = fmaxf(mx, fmaxf(fmaxf(x.x, x.y), fmaxf(x.z, x.w)));
            }
#pragma unroll
            for (int o = 16; o > 0; o >>= 1)
                mx = fmaxf(mx, __shfl_xor_sync(0xffffffffu, mx, o));
            float s = 0.f;
            for (int u = lane; u < 256; u += 32) {
                float4 x = pr[u];
                x.x = fexp(x.x - mx); x.y = fexp(x.y - mx);
                x.z = fexp(x.z - mx); x.w = fexp(x.w - mx);
                s += (x.x + x.y) + (x.z + x.w);
                pr[u] = x;
            }
#pragma unroll
            for (int o = 16; o > 0; o >>= 1)
                s += __shfl_xor_sync(0xffffffffu, s, o);
            if (lane == 0) inv[row] = 1.0f / s;
        }
        __syncthreads();

        // ========== attn-sum: accumulate p/H directly into gmem =============
        {
            float4* out4 = reinterpret_cast<float4*>(attn_out + mrow0);
            const float4* sc4 = reinterpret_cast<const float4*>(score);
#pragma unroll
            for (int u = 0; u < 16; u++) {
                float sv = inv[u] * 0.125f;
                ull s2 = pack2(sv, sv);
                float4 ev = sc4[u * 256 + t];
                const ull* ep = reinterpret_cast<const ull*>(&ev);
                float4 o;
                ull* op = reinterpret_cast<ull*>(&o);
                if (h == 0) {
                    op[0] = fma2(ep[0], s2, 0ull);
                    op[1] = fma2(ep[1], s2, 0ull);
                } else {
                    float4 ov = out4[u * 256 + t];
                    const ull* vp = reinterpret_cast<const ull*>(&ov);
                    op[0] = fma2(ep[0], s2, vp[0]);
                    op[1] = fma2(ep[1], s2, vp[1]);
                }
                out4[u * 256 + t] = o;
            }
        }

        // ================= PV phase =================
        // prefetch v tile 0: thread owns d=lane, s = w*4 + j + 32u
        float vreg[16];
#pragma unroll
        for (int u = 0; u < 4; u++)
#pragma unroll
            for (int j = 0; j < 4; j++) {
                int s = w * 4 + j + 32 * u;
                vreg[u * 4 + j] =
                    g_vh[((size_t)(b * S_ + s)) * D_ + h * 32 + lane];
            }

        ull accv[4];
#pragma unroll
        for (int r = 0; r < 4; r++) accv[r] = 0ull;

        for (int st = 0; st < 8; st++) {
            __syncthreads();   // vtT free
            // STS transposed v tile: vtT[d][s]
#pragma unroll
            for (int u = 0; u < 4; u++) {
                float4 x = make_float4(vreg[u*4+0], vreg[u*4+1], vreg[u*4+2], vreg[u*4+3]);
                *reinterpret_cast<float4*>(&vtT[lane * 132 + w * 4 + 32 * u]) = x;
            }
            __syncthreads();
            if (st < 7) {
#pragma unroll
                for (int u = 0; u < 4; u++)
#pragma unroll
                    for (int j = 0; j < 4; j++) {
                        int s = (st + 1) * 128 + w * 4 + j + 32 * u;
                        vreg[u * 4 + j] =
                            g_vh[((size_t)(b * S_ + s)) * D_ + h * 32 + lane];
                    }
            }

            // compute: 4 rows, 64 s (this warp's half), FFMA2 over s-pairs
#pragma unroll 4
            for (int s4 = 0; s4 < 16; s4++) {
                float4 vf = *reinterpret_cast<const float4*>(
                    &vtT[lane * 132 + ch * 64 + s4 * 4]);
                const ull* vp = reinterpret_cast<const ull*>(&vf);
#pragma unroll
                for (int r = 0; r < 4; r++) {
                    float4 ef = *reinterpret_cast<const float4*>(
                        &score[((rg4 + r) << 10) + st * 128 + ch * 64 + s4 * 4]);
                    const ull* ep = reinterpret_cast<const ull*>(&ef);
                    accv[r] = fma2(vp[0], ep[0], accv[r]);
                    accv[r] = fma2(vp[1], ep[1], accv[r]);
                }
            }
        }

        // partials -> smem (q buffers are dead now)
        {
            float* part = ch ? qos : qss;
#pragma unroll
            for (int r = 0; r < 4; r++) {
                float2 f = unpack2(accv[r]);
                part[(rg4 + r) * 32 + lane] = f.x + f.y;
            }
        }
        __syncthreads();

        // combine halves, normalize, write ctx
#pragma unroll
        for (int u = 0; u < 2; u++) {
            int idx = t + 256 * u;
            int row = idx >> 5, d = idx & 31;
            float val = (qss[idx] + qos[idx]) * inv[row];
            g_ctx[((size_t)(b * L_ + l0 + row)) * V_ + h * 32 + d] = val;
        }
    }
}

// ---------------------------------------------------------------------------
extern "C" void kernel_launch(void* const* d_in, const int* in_sizes, int n_in,
                              void* d_out, int out_size)
{
    const float* q    = (const float*)d_in[0];
    const float* k    = (const float*)d_in[1];
    const float* v    = (const float*)d_in[2];
    const int*   qid  = (const int*)d_in[3];
    const int*   kid  = (const int*)d_in[4];
    const float* mask = (const float*)d_in[5];
    const float* wqs  = (const float*)d_in[6];
    const float* wqo  = (const float*)d_in[7];
    const float* wks  = (const float*)d_in[8];
    const float* wko  = (const float*)d_in[9];
    const float* wv   = (const float*)d_in[10];
    const float* fcw  = (const float*)d_in[11];
    const float* fcb  = (const float*)d_in[12];

    float* out      = (float*)d_out;
    float* attn_out = out + (size_t)B_ * L_ * V_;

    void *p_qs, *p_qo, *p_ks, *p_ko, *p_vh, *p_ctx;
    cudaGetSymbolAddress(&p_qs,  g_qs);
    cudaGetSymbolAddress(&p_qo,  g_qo);
    cudaGetSymbolAddress(&p_ks,  g_ks);
    cudaGetSymbolAddress(&p_ko,  g_ko);
    cudaGetSymbolAddress(&p_vh,  g_vh);
    cudaGetSymbolAddress(&p_ctx, g_ctx);

    cudaFuncSetAttribute(attn_kernel,
                         cudaFuncAttributeMaxDynamicSharedMemorySize,
                         AT_SMEM_BYTES);

    Proj5 p;
    p.A[0] = q;  p.W[0] = wqs; p.C[0] = (float*)p_qs; p.sc[0] = SCALE_F;
    p.A[1] = q;  p.W[1] = wqo; p.C[1] = (float*)p_qo; p.sc[1] = SCALE_F;
    p.A[2] = k;  p.W[2] = wks; p.C[2] = (float*)p_ks; p.sc[2] = 1.0f;
    p.A[3] = k;  p.W[3] = wko; p.C[3] = (float*)p_ko; p.sc[3] = 1.0f;
    p.A[4] = v;  p.W[4] = wv;  p.C[4] = (float*)p_vh; p.sc[4] = 1.0f;

    dim3 pgrid(V_ / 64, N_TOK / 128, 5);
    proj_kernel<<<pgrid, 256>>>(p);

    dim3 agrid(L_ / 16, B_);
    attn_kernel<<<agrid, 256, AT_SMEM_BYTES>>>(mask, qid, kid, attn_out);

    dim3 fgrid(V_ / 64, N_TOK / 128);
    fc_kernel<<<fgrid, 256>>>((const float*)p_ctx, fcw, fcb, out);
}

// round 4
// speedup vs baseline: 2.9709x; 1.4675x over previous
#include <cuda_runtime.h>
#include <math_constants.h>

#define B_  8
#define L_  1024
#define S_  1024
#define D_  256
#define V_  256
#define H_  8

#define N_TOK (B_*L_)
#define SCALE_F 0.17677669529663687f

// ---------------- scratch (static device arrays: allocation-free) ----------
__device__ float g_qs[N_TOK*D_];
__device__ float g_qo[N_TOK*D_];
__device__ float g_ks[N_TOK*D_];
__device__ float g_ko[N_TOK*D_];
__device__ float g_vh[N_TOK*D_];
__device__ float g_ctx[N_TOK*V_];

// ---------------- fast exp on FMA pipe (rel err ~2e-6) ---------------------
__device__ __forceinline__ float fexp(float x)
{
    float t = fmaxf(x * 1.4426950408889634f, -125.0f);
    float r = rintf(t);
    float f = t - r;
    float p = 1.3333558146428443e-3f;
    p = fmaf(p, f, 9.6181291076284772e-3f);
    p = fmaf(p, f, 5.5504108664821580e-2f);
    p = fmaf(p, f, 2.4022650695910071e-1f);
    p = fmaf(p, f, 6.9314718055994531e-1f);
    p = fmaf(p, f, 1.0f);
    return __int_as_float(__float_as_int(p) + (((int)r) << 23));
}

// ---------------- tf32 mma helpers -----------------------------------------
__device__ __forceinline__ unsigned cvt_tf32(float f)
{
    unsigned r;
    asm("cvt.rna.tf32.f32 %0, %1;" : "=r"(r) : "f"(f));
    return r;
}

__device__ __forceinline__ void mma_tf32(float c[4], const unsigned a[4],
                                         const unsigned b[2])
{
    asm("mma.sync.aligned.m16n8k8.row.col.f32.tf32.tf32.f32 "
        "{%0,%1,%2,%3}, {%4,%5,%6,%7}, {%8,%9}, {%0,%1,%2,%3};"
        : "+f"(c[0]), "+f"(c[1]), "+f"(c[2]), "+f"(c[3])
        : "r"(a[0]), "r"(a[1]), "r"(a[2]), "r"(a[3]),
          "r"(b[0]), "r"(b[1]));
}

// ---------------------------------------------------------------------------
// GEMM (R2-proven fp32 version): C = scale*(A @ Bw^T) + bias
// BM=128, BN=64, BK=16, 256 threads, 8x4 register tile.
// ---------------------------------------------------------------------------
__device__ __forceinline__ void gemm_body(
    const float* __restrict__ A, const float* __restrict__ Bw,
    float* __restrict__ C, int N, int K,
    float scale, const float* __restrict__ bias)
{
    const int BM = 128, BN = 64, BK = 16;
    __shared__ __align__(16) float As[BK][BM + 4];
    __shared__ __align__(16) float Bs[BK][BN + 4];

    int t  = threadIdx.x;
    int m0 = blockIdx.y * BM;
    int n0 = blockIdx.x * BN;
    int tx = t & 15;
    int ty = t >> 4;

    float acc[8][4];
#pragma unroll
    for (int i = 0; i < 8; i++)
#pragma unroll
        for (int j = 0; j < 4; j++) acc[i][j] = 0.f;

    for (int k0 = 0; k0 < K; k0 += BK) {
#pragma unroll
        for (int i = 0; i < 2; i++) {
            int f  = t + i * 256;
            int r  = f >> 2;
            int c4 = (f & 3) * 4;
            float4 vv = *reinterpret_cast<const float4*>(
                &A[(size_t)(m0 + r) * K + k0 + c4]);
            As[c4 + 0][r] = vv.x;
            As[c4 + 1][r] = vv.y;
            As[c4 + 2][r] = vv.z;
            As[c4 + 3][r] = vv.w;
        }
        {
            int r  = t >> 2;
            int c4 = (t & 3) * 4;
            float4 vv = *reinterpret_cast<const float4*>(
                &Bw[(size_t)(n0 + r) * K + k0 + c4]);
            Bs[c4 + 0][r] = vv.x;
            Bs[c4 + 1][r] = vv.y;
            Bs[c4 + 2][r] = vv.z;
            Bs[c4 + 3][r] = vv.w;
        }
        __syncthreads();

#pragma unroll
        for (int k = 0; k < BK; k++) {
            float4 a0 = *reinterpret_cast<const float4*>(&As[k][ty * 8]);
            float4 a1 = *reinterpret_cast<const float4*>(&As[k][ty * 8 + 4]);
            float4 b0 = *reinterpret_cast<const float4*>(&Bs[k][tx * 4]);
            float a[8] = {a0.x, a0.y, a0.z, a0.w, a1.x, a1.y, a1.z, a1.w};
            float bb[4] = {b0.x, b0.y, b0.z, b0.w};
#pragma unroll
            for (int i = 0; i < 8; i++)
#pragma unroll
                for (int j = 0; j < 4; j++) acc[i][j] += a[i] * bb[j];
        }
        __syncthreads();
    }

    float bv[4] = {0.f, 0.f, 0.f, 0.f};
    if (bias) {
#pragma unroll
        for (int j = 0; j < 4; j++) bv[j] = bias[n0 + tx * 4 + j];
    }
#pragma unroll
    for (int i = 0; i < 8; i++) {
        int row = m0 + ty * 8 + i;
        float4 o;
        o.x = acc[i][0] * scale + bv[0];
        o.y = acc[i][1] * scale + bv[1];
        o.z = acc[i][2] * scale + bv[2];
        o.w = acc[i][3] * scale + bv[3];
        *reinterpret_cast<float4*>(&C[(size_t)row * N + n0 + tx * 4]) = o;
    }
}

struct Proj5 {
    const float* A[5];
    const float* W[5];
    float*       C[5];
    float        sc[5];
};

__global__ __launch_bounds__(256, 3)
void proj_kernel(Proj5 p)
{
    int z = blockIdx.z;
    gemm_body(p.A[z], p.W[z], p.C[z], D_, D_, p.sc[z], nullptr);
}

__global__ __launch_bounds__(256, 3)
void fc_kernel(const float* __restrict__ A, const float* __restrict__ W,
               const float* __restrict__ bias, float* __restrict__ C)
{
    gemm_body(A, W, C, V_, V_, 1.0f, bias);
}

// ---------------------------------------------------------------------------
// Attention (tensor-core tf32): block = (b, 16 l-rows), 256 threads, 2/SM.
// smem floats:
//   score [16][1036] = 16576   (pad 1036: conflict-free MMA A-frag reads)
//   kst   [128][36]  = 4608    (aliased by vt[128][40] and red[8][512] later)
//   kot   [128][36]  = 4608
//   inv 16 | qid 16(int) | kid 1024(int)
// total 26848 floats = 107392 B  -> 2 blocks/SM
// ---------------------------------------------------------------------------
#define SC_STR 1036
#define AT_SMEM_FLOATS (16*SC_STR + 4608 + 4608 + 16 + 16 + 1024)
#define AT_SMEM_BYTES  (AT_SMEM_FLOATS * 4)

__global__ __launch_bounds__(256, 2)
void attn_kernel(const float* __restrict__ mask,
                 const int* __restrict__ qid,
                 const int* __restrict__ kid,
                 float* __restrict__ attn_out)
{
    extern __shared__ float sm[];
    float* score = sm;                       // [16][1036]
    float* kst   = sm + 16 * SC_STR;         // [128][36]
    float* kot   = kst + 4608;               // [128][36]
    float* vt    = kst;                      // alias: [128][40] (PV)
    float* red   = kst;                      // alias: [8][512]  (PV reduce)
    float* inv   = kot + 4608;               // [16]
    int*   qid_s = (int*)(inv + 16);         // [16]
    int*   kid_s = qid_s + 16;               // [1024]

    const int b    = blockIdx.y;
    const int l0   = blockIdx.x * 16;
    const int t    = threadIdx.x;
    const int lane = t & 31;
    const int w    = t >> 5;
    const int gid  = lane >> 2;              // MMA groupID
    const int tid4 = lane & 3;               // MMA thread-in-group

    const size_t qbase = (size_t)(b * L_ + l0);
    const size_t mrow0 = qbase * S_;

    for (int i = t; i < S_; i += 256) kid_s[i] = kid[b * S_ + i];
    if (t < 16) qid_s[t] = qid[b * L_ + l0 + t];

    for (int h = 0; h < H_; h++) {
        __syncthreads();   // prior head fully done (red reads, score free)

        // ---- A fragments (q self/other) straight from gmem, tf32 ----
        unsigned aS[4][4], aO[4][4];
#pragma unroll
        for (int ks = 0; ks < 4; ks++) {
            int kk = h * 32 + ks * 8 + tid4;
            const float* q0 = g_qs + (qbase + gid) * D_ + kk;
            const float* q1 = g_qs + (qbase + gid + 8) * D_ + kk;
            aS[ks][0] = cvt_tf32(q0[0]);
            aS[ks][1] = cvt_tf32(q1[0]);
            aS[ks][2] = cvt_tf32(q0[4]);
            aS[ks][3] = cvt_tf32(q1[4]);
            const float* o0 = g_qo + (qbase + gid) * D_ + kk;
            const float* o1 = g_qo + (qbase + gid + 8) * D_ + kk;
            aO[ks][0] = cvt_tf32(o0[0]);
            aO[ks][1] = cvt_tf32(o1[0]);
            aO[ks][2] = cvt_tf32(o0[4]);
            aO[ks][3] = cvt_tf32(o1[4]);
        }

        // ---- prefetch k tiles (st=0) ----
        float4 kreg[8];
#pragma unroll
        for (int u = 0; u < 8; u++) {
            int f = t + 256 * u;
            int r = (f >> 3) & 127, c4 = (f & 7) * 4;
            const float* src = (f >> 10) ? g_ko : g_ks;
            kreg[u] = *reinterpret_cast<const float4*>(
                &src[((size_t)(b * S_ + r)) * D_ + h * 32 + c4]);
        }

        // ================= score phase =================
        for (int st = 0; st < 8; st++) {
            __syncthreads();   // tile buffers free, prev epilogue done
#pragma unroll
            for (int u = 0; u < 8; u++) {
                int f = t + 256 * u;
                int r = (f >> 3) & 127, c4 = (f & 7) * 4;
                float* dst = (f >> 10) ? kot : kst;
                *reinterpret_cast<float4*>(&dst[r * 36 + c4]) = kreg[u];
            }
            // prefill this score tile with mask
#pragma unroll
            for (int u = 0; u < 2; u++) {
                int f = t + 256 * u;
                int row = f >> 5, c4 = (f & 31) * 4;
                float4 mv = *reinterpret_cast<const float4*>(
                    &mask[mrow0 + (size_t)row * S_ + st * 128 + c4]);
                *reinterpret_cast<float4*>(
                    &score[row * SC_STR + st * 128 + c4]) = mv;
            }
            __syncthreads();

            if (st < 7) {
#pragma unroll
                for (int u = 0; u < 8; u++) {
                    int f = t + 256 * u;
                    int r = (f >> 3) & 127, c4 = (f & 7) * 4;
                    const float* src = (f >> 10) ? g_ko : g_ks;
                    kreg[u] = *reinterpret_cast<const float4*>(
                        &src[((size_t)(b * S_ + (st + 1) * 128 + r)) * D_ +
                             h * 32 + c4]);
                }
            }

            float cS[2][4] = {{0,0,0,0},{0,0,0,0}};
            float cO[2][4] = {{0,0,0,0},{0,0,0,0}};
#pragma unroll
            for (int ks = 0; ks < 4; ks++) {
#pragma unroll
                for (int nt = 0; nt < 2; nt++) {
                    int sK = w * 16 + nt * 8 + gid;
                    int d  = ks * 8 + tid4;
                    unsigned bb[2];
                    bb[0] = cvt_tf32(kst[sK * 36 + d]);
                    bb[1] = cvt_tf32(kst[sK * 36 + d + 4]);
                    mma_tf32(cS[nt], aS[ks], bb);
                    bb[0] = cvt_tf32(kot[sK * 36 + d]);
                    bb[1] = cvt_tf32(kot[sK * 36 + d + 4]);
                    mma_tf32(cO[nt], aO[ks], bb);
                }
            }

            // select + add mask (RMW into prefilled score)
#pragma unroll
            for (int nt = 0; nt < 2; nt++) {
                int scol = st * 128 + w * 16 + nt * 8 + 2 * tid4;
                int ki0 = kid_s[scol], ki1 = kid_s[scol + 1];
#pragma unroll
                for (int r = 0; r < 4; r++) {
                    int row = gid + ((r >> 1) << 3);
                    int col = scol + (r & 1);
                    int ki  = (r & 1) ? ki1 : ki0;
                    float val = (qid_s[row] == ki) ? cS[nt][r] : cO[nt][r];
                    score[row * SC_STR + col] += val;
                }
            }
        }
        __syncthreads();

        // ================= softmax (warp w: rows 2w, 2w+1) ==================
#pragma unroll
        for (int rr = 0; rr < 2; rr++) {
            int row = 2 * w + rr;
            float4* pr = (float4*)(score + row * SC_STR);
            float mx = -CUDART_INF_F;
            for (int u = lane; u < 256; u += 32) {
                float4 x = pr[u];
                mx = fmaxf(mx, fmaxf(fmaxf(x.x, x.y), fmaxf(x.z, x.w)));
            }
#pragma unroll
            for (int o = 16; o > 0; o >>= 1)
                mx = fmaxf(mx, __shfl_xor_sync(0xffffffffu, mx, o));
            float s = 0.f;
            for (int u = lane; u < 256; u += 32) {
                float4 x = pr[u];
                x.x = fexp(x.x - mx); x.y = fexp(x.y - mx);
                x.z = fexp(x.z - mx); x.w = fexp(x.w - mx);
                s += (x.x + x.y) + (x.z + x.w);
                pr[u] = x;
            }
#pragma unroll
            for (int o = 16; o > 0; o >>= 1)
                s += __shfl_xor_sync(0xffffffffu, s, o);
            if (lane == 0) inv[row] = 1.0f / s;
        }
        __syncthreads();

        // ---- prefetch v tile 0 (overlaps attn-sum below) ----
        float4 vreg[4];
#pragma unroll
        for (int u = 0; u < 4; u++) {
            int f = t + 256 * u;
            int r = f >> 3, c4 = (f & 7) * 4;
            vreg[u] = *reinterpret_cast<const float4*>(
                &g_vh[((size_t)(b * S_ + r)) * D_ + h * 32 + c4]);
        }

        // ---- attn-sum: accumulate p/H into gmem ----
        {
            float4* out4 = reinterpret_cast<float4*>(attn_out + mrow0);
#pragma unroll
            for (int u = 0; u < 16; u++) {
                float sv = inv[u] * 0.125f;
                float4 ev = *reinterpret_cast<const float4*>(
                    &score[u * SC_STR + t * 4]);
                float4 o;
                if (h == 0) {
                    o.x = ev.x * sv; o.y = ev.y * sv;
                    o.z = ev.z * sv; o.w = ev.w * sv;
                } else {
                    float4 ov = out4[u * 256 + t];
                    o.x = fmaf(ev.x, sv, ov.x);
                    o.y = fmaf(ev.y, sv, ov.y);
                    o.z = fmaf(ev.z, sv, ov.z);
                    o.w = fmaf(ev.w, sv, ov.w);
                }
                out4[u * 256 + t] = o;
            }
        }

        // ================= PV phase (tf32 mma) =================
        float cv[4][4] = {{0,0,0,0},{0,0,0,0},{0,0,0,0},{0,0,0,0}};

        for (int st = 0; st < 8; st++) {
            __syncthreads();   // vt buffer free
#pragma unroll
            for (int u = 0; u < 4; u++) {
                int f = t + 256 * u;
                int r = f >> 3, c4 = (f & 7) * 4;
                *reinterpret_cast<float4*>(&vt[r * 40 + c4]) = vreg[u];
            }
            __syncthreads();
            if (st < 7) {
#pragma unroll
                for (int u = 0; u < 4; u++) {
                    int f = t + 256 * u;
                    int r = f >> 3, c4 = (f & 7) * 4;
                    vreg[u] = *reinterpret_cast<const float4*>(
                        &g_vh[((size_t)(b * S_ + (st + 1) * 128 + r)) * D_ +
                              h * 32 + c4]);
                }
            }

#pragma unroll
            for (int i = 0; i < 2; i++) {
                int kl = (w * 2 + i) * 8;       // k-step within tile
                int sb = st * 128 + kl;
                unsigned av[4];
                av[0] = cvt_tf32(score[gid * SC_STR + sb + tid4]);
                av[1] = cvt_tf32(score[(gid + 8) * SC_STR + sb + tid4]);
                av[2] = cvt_tf32(score[gid * SC_STR + sb + tid4 + 4]);
                av[3] = cvt_tf32(score[(gid + 8) * SC_STR + sb + tid4 + 4]);
#pragma unroll
                for (int nt = 0; nt < 4; nt++) {
                    unsigned bv[2];
                    bv[0] = cvt_tf32(vt[(kl + tid4) * 40 + nt * 8 + gid]);
                    bv[1] = cvt_tf32(vt[(kl + tid4 + 4) * 40 + nt * 8 + gid]);
                    mma_tf32(cv[nt], av, bv);
                }
            }
        }
        __syncthreads();   // vt reads done -> red free

        // partial C -> smem, cross-warp reduce, write ctx (normalized)
#pragma unroll
        for (int nt = 0; nt < 4; nt++)
#pragma unroll
            for (int r = 0; r < 4; r++) {
                int row = gid + ((r >> 1) << 3);
                int col = nt * 8 + 2 * tid4 + (r & 1);
                red[w * 512 + row * 32 + col] = cv[nt][r];
            }
        __syncthreads();
#pragma unroll
        for (int u = 0; u < 2; u++) {
            int e = t + 256 * u;
            int row = e >> 5, d = e & 31;
            float s = 0.f;
#pragma unroll
            for (int wi = 0; wi < 8; wi++) s += red[wi * 512 + e];
            g_ctx[(qbase + row) * V_ + h * 32 + d] = s * inv[row];
        }
    }
}

// ---------------------------------------------------------------------------
extern "C" void kernel_launch(void* const* d_in, const int* in_sizes, int n_in,
                              void* d_out, int out_size)
{
    const float* q    = (const float*)d_in[0];
    const float* k    = (const float*)d_in[1];
    const float* v    = (const float*)d_in[2];
    const int*   qid  = (const int*)d_in[3];
    const int*   kid  = (const int*)d_in[4];
    const float* mask = (const float*)d_in[5];
    const float* wqs  = (const float*)d_in[6];
    const float* wqo  = (const float*)d_in[7];
    const float* wks  = (const float*)d_in[8];
    const float* wko  = (const float*)d_in[9];
    const float* wv   = (const float*)d_in[10];
    const float* fcw  = (const float*)d_in[11];
    const float* fcb  = (const float*)d_in[12];

    float* out      = (float*)d_out;
    float* attn_out = out + (size_t)B_ * L_ * V_;

    void *p_qs, *p_qo, *p_ks, *p_ko, *p_vh, *p_ctx;
    cudaGetSymbolAddress(&p_qs,  g_qs);
    cudaGetSymbolAddress(&p_qo,  g_qo);
    cudaGetSymbolAddress(&p_ks,  g_ks);
    cudaGetSymbolAddress(&p_ko,  g_ko);
    cudaGetSymbolAddress(&p_vh,  g_vh);
    cudaGetSymbolAddress(&p_ctx, g_ctx);

    cudaFuncSetAttribute(attn_kernel,
                         cudaFuncAttributeMaxDynamicSharedMemorySize,
                         AT_SMEM_BYTES);

    Proj5 p;
    p.A[0] = q;  p.W[0] = wqs; p.C[0] = (float*)p_qs; p.sc[0] = SCALE_F;
    p.A[1] = q;  p.W[1] = wqo; p.C[1] = (float*)p_qo; p.sc[1] = SCALE_F;
    p.A[2] = k;  p.W[2] = wks; p.C[2] = (float*)p_ks; p.sc[2] = 1.0f;
    p.A[3] = k;  p.W[3] = wko; p.C[3] = (float*)p_ko; p.sc[3] = 1.0f;
    p.A[4] = v;  p.W[4] = wv;  p.C[4] = (float*)p_vh; p.sc[4] = 1.0f;

    dim3 pgrid(V_ / 64, N_TOK / 128, 5);
    proj_kernel<<<pgrid, 256>>>(p);

    dim3 agrid(L_ / 16, B_);
    attn_kernel<<<agrid, 256, AT_SMEM_BYTES>>>(mask, qid, kid, attn_out);

    dim3 fgrid(V_ / 64, N_TOK / 128);
    fc_kernel<<<fgrid, 256>>>((const float*)p_ctx, fcw, fcb, out);
}

// round 5
// speedup vs baseline: 3.2016x; 1.0776x over previous
#include <cuda_runtime.h>
#include <math_constants.h>

#define B_  8
#define L_  1024
#define S_  1024
#define D_  256
#define V_  256
#define H_  8

#define N_TOK (B_*L_)
#define SCALE_F 0.17677669529663687f

// ---------------- scratch (static device arrays: allocation-free) ----------
__device__ float g_qs[N_TOK*D_];
__device__ float g_qo[N_TOK*D_];
__device__ float g_ks[N_TOK*D_];
__device__ float g_ko[N_TOK*D_];
__device__ float g_vh[N_TOK*D_];
__device__ float g_ctx[N_TOK*V_];

// ---------------- fast exp on FMA pipe (rel err ~2e-6) ---------------------
__device__ __forceinline__ float fexp(float x)
{
    float t = fmaxf(x * 1.4426950408889634f, -125.0f);
    float r = rintf(t);
    float f = t - r;
    float p = 1.3333558146428443e-3f;
    p = fmaf(p, f, 9.6181291076284772e-3f);
    p = fmaf(p, f, 5.5504108664821580e-2f);
    p = fmaf(p, f, 2.4022650695910071e-1f);
    p = fmaf(p, f, 6.9314718055994531e-1f);
    p = fmaf(p, f, 1.0f);
    return __int_as_float(__float_as_int(p) + (((int)r) << 23));
}

// ---------------- tf32 mma helpers -----------------------------------------
__device__ __forceinline__ unsigned cvt_tf32(float f)
{
    unsigned r;
    asm("cvt.rna.tf32.f32 %0, %1;" : "=r"(r) : "f"(f));
    return r;
}

__device__ __forceinline__ void mma_tf32(float c[4], const unsigned a[4],
                                         const unsigned b[2])
{
    asm("mma.sync.aligned.m16n8k8.row.col.f32.tf32.tf32.f32 "
        "{%0,%1,%2,%3}, {%4,%5,%6,%7}, {%8,%9}, {%0,%1,%2,%3};"
        : "+f"(c[0]), "+f"(c[1]), "+f"(c[2]), "+f"(c[3])
        : "r"(a[0]), "r"(a[1]), "r"(a[2]), "r"(a[3]),
          "r"(b[0]), "r"(b[1]));
}

// ---------------------------------------------------------------------------
// GEMM (R2-proven fp32): C = scale*(A @ Bw^T) + bias.  BM=128 BN=64 BK=16.
// ---------------------------------------------------------------------------
__device__ __forceinline__ void gemm_body(
    const float* __restrict__ A, const float* __restrict__ Bw,
    float* __restrict__ C, int N, int K,
    float scale, const float* __restrict__ bias)
{
    const int BM = 128, BN = 64, BK = 16;
    __shared__ __align__(16) float As[BK][BM + 4];
    __shared__ __align__(16) float Bs[BK][BN + 4];

    int t  = threadIdx.x;
    int m0 = blockIdx.y * BM;
    int n0 = blockIdx.x * BN;
    int tx = t & 15;
    int ty = t >> 4;

    float acc[8][4];
#pragma unroll
    for (int i = 0; i < 8; i++)
#pragma unroll
        for (int j = 0; j < 4; j++) acc[i][j] = 0.f;

    for (int k0 = 0; k0 < K; k0 += BK) {
#pragma unroll
        for (int i = 0; i < 2; i++) {
            int f  = t + i * 256;
            int r  = f >> 2;
            int c4 = (f & 3) * 4;
            float4 vv = *reinterpret_cast<const float4*>(
                &A[(size_t)(m0 + r) * K + k0 + c4]);
            As[c4 + 0][r] = vv.x;
            As[c4 + 1][r] = vv.y;
            As[c4 + 2][r] = vv.z;
            As[c4 + 3][r] = vv.w;
        }
        {
            int r  = t >> 2;
            int c4 = (t & 3) * 4;
            float4 vv = *reinterpret_cast<const float4*>(
                &Bw[(size_t)(n0 + r) * K + k0 + c4]);
            Bs[c4 + 0][r] = vv.x;
            Bs[c4 + 1][r] = vv.y;
            Bs[c4 + 2][r] = vv.z;
            Bs[c4 + 3][r] = vv.w;
        }
        __syncthreads();

#pragma unroll
        for (int k = 0; k < BK; k++) {
            float4 a0 = *reinterpret_cast<const float4*>(&As[k][ty * 8]);
            float4 a1 = *reinterpret_cast<const float4*>(&As[k][ty * 8 + 4]);
            float4 b0 = *reinterpret_cast<const float4*>(&Bs[k][tx * 4]);
            float a[8] = {a0.x, a0.y, a0.z, a0.w, a1.x, a1.y, a1.z, a1.w};
            float bb[4] = {b0.x, b0.y, b0.z, b0.w};
#pragma unroll
            for (int i = 0; i < 8; i++)
#pragma unroll
                for (int j = 0; j < 4; j++) acc[i][j] += a[i] * bb[j];
        }
        __syncthreads();
    }

    float bv[4] = {0.f, 0.f, 0.f, 0.f};
    if (bias) {
#pragma unroll
        for (int j = 0; j < 4; j++) bv[j] = bias[n0 + tx * 4 + j];
    }
#pragma unroll
    for (int i = 0; i < 8; i++) {
        int row = m0 + ty * 8 + i;
        float4 o;
        o.x = acc[i][0] * scale + bv[0];
        o.y = acc[i][1] * scale + bv[1];
        o.z = acc[i][2] * scale + bv[2];
        o.w = acc[i][3] * scale + bv[3];
        *reinterpret_cast<float4*>(&C[(size_t)row * N + n0 + tx * 4]) = o;
    }
}

struct Proj5 {
    const float* A[5];
    const float* W[5];
    float*       C[5];
    float        sc[5];
};

__global__ __launch_bounds__(256, 3)
void proj_kernel(Proj5 p)
{
    int z = blockIdx.z;
    gemm_body(p.A[z], p.W[z], p.C[z], D_, D_, p.sc[z], nullptr);
}

__global__ __launch_bounds__(256, 3)
void fc_kernel(const float* __restrict__ A, const float* __restrict__ W,
               const float* __restrict__ bias, float* __restrict__ C)
{
    gemm_body(A, W, C, V_, V_, 1.0f, bias);
}

// ---------------------------------------------------------------------------
// Attention (tf32 mma): block = (b, 32 l-rows), 512 threads, 1 block/SM.
// smem floats:
//   score [32][1036] = 33152  (stride 1036: conflict-free A-frag reads;
//                              aliased by red[8][32][36] after PV)
//   ktile 2buf x 2mat x [128][36] = 18432  (aliased by vt 2buf x [128][40])
//   inv 32 | qid 32(int) | kid 1024(int)
// total 210,688 B  -> 1 block/SM (227KB carveout)
// ---------------------------------------------------------------------------
#define SC_STR 1036
#define AT_SMEM_BYTES ((33152 + 18432 + 32 + 32 + 1024) * 4)

__global__ __launch_bounds__(512, 1)
void attn_kernel(const float* __restrict__ mask,
                 const int* __restrict__ qid,
                 const int* __restrict__ kid,
                 float* __restrict__ attn_out)
{
    extern __shared__ float sm[];
    float* score = sm;                        // [32][1036]
    float* ktile = sm + 32 * SC_STR;          // 2x2x[128][36]
    float* red   = sm;                        // alias: [8][32][36] (PV reduce)
    float* inv   = ktile + 18432;             // [32]
    int*   qid_s = (int*)(inv + 32);          // [32]
    int*   kid_s = qid_s + 32;                // [1024]

    const int b    = blockIdx.y;
    const int l0   = blockIdx.x * 32;
    const int t    = threadIdx.x;
    const int lane = t & 31;
    const int w    = t >> 5;                  // 0..15
    const int gid  = lane >> 2;
    const int tid4 = lane & 3;
    const int wr   = w & 1;                   // row m16-tile (0: rows 0-15, 1: 16-31)
    const int wc   = w >> 1;                  // 16-col group / PV s-chunk

    const size_t qbase = (size_t)(b * L_ + l0);
    const size_t mrow0 = qbase * S_;

    for (int i = t; i < S_; i += 512) kid_s[i] = kid[b * S_ + i];
    if (t < 32) qid_s[t] = qid[b * L_ + l0 + t];

    for (int h = 0; h < H_; h++) {
        __syncthreads();   // prev head fully done (red/ctx reads); ids visible

        // ---- A fragments (q self/other) straight from gmem ----
        unsigned aS[4][4], aO[4][4];
        {
            const size_t r0 = (qbase + wr * 16 + gid) * D_;
            const size_t r1 = (qbase + wr * 16 + gid + 8) * D_;
#pragma unroll
            for (int ks = 0; ks < 4; ks++) {
                int kk = h * 32 + ks * 8 + tid4;
                aS[ks][0] = cvt_tf32(g_qs[r0 + kk]);
                aS[ks][1] = cvt_tf32(g_qs[r1 + kk]);
                aS[ks][2] = cvt_tf32(g_qs[r0 + kk + 4]);
                aS[ks][3] = cvt_tf32(g_qs[r1 + kk + 4]);
                aO[ks][0] = cvt_tf32(g_qo[r0 + kk]);
                aO[ks][1] = cvt_tf32(g_qo[r1 + kk]);
                aO[ks][2] = cvt_tf32(g_qo[r0 + kk + 4]);
                aO[ks][3] = cvt_tf32(g_qo[r1 + kk + 4]);
            }
        }

        // ---- mask prefill: score <- mask (whole 32x1024 strip) ----
#pragma unroll
        for (int u = 0; u < 16; u++) {
            int f = t + 512 * u;
            int row = f >> 8, c4 = (f & 255) * 4;
            float4 mv = *reinterpret_cast<const float4*>(
                &mask[mrow0 + (size_t)row * S_ + c4]);
            *reinterpret_cast<float4*>(&score[row * SC_STR + c4]) = mv;
        }

        // ---- k prefetch tile 0 ----
        float4 kreg[4];
#pragma unroll
        for (int u = 0; u < 4; u++) {
            int f = t + 512 * u;                  // 0..2047
            int mat = f >> 10, r = (f >> 3) & 127, c4 = (f & 7) * 4;
            const float* src = mat ? g_ko : g_ks;
            kreg[u] = *reinterpret_cast<const float4*>(
                &src[((size_t)(b * S_ + r)) * D_ + h * 32 + c4]);
        }
#pragma unroll
        for (int u = 0; u < 4; u++) {
            int f = t + 512 * u;
            int mat = f >> 10, r = (f >> 3) & 127, c4 = (f & 7) * 4;
            *reinterpret_cast<float4*>(&ktile[mat * 4608 + r * 36 + c4]) = kreg[u];
        }
        __syncthreads();

        // ================= score phase (double-buffered k) =================
        for (int st = 0; st < 8; st++) {
            const int cur = st & 1;
            if (st < 7) {
#pragma unroll
                for (int u = 0; u < 4; u++) {
                    int f = t + 512 * u;
                    int mat = f >> 10, r = (f >> 3) & 127, c4 = (f & 7) * 4;
                    const float* src = mat ? g_ko : g_ks;
                    kreg[u] = *reinterpret_cast<const float4*>(
                        &src[((size_t)(b * S_ + (st + 1) * 128 + r)) * D_ +
                             h * 32 + c4]);
                }
            }

            const float* kbS = ktile + (cur * 2 + 0) * 4608;
            const float* kbO = ktile + (cur * 2 + 1) * 4608;

            float cS[2][4] = {{0,0,0,0},{0,0,0,0}};
            float cO[2][4] = {{0,0,0,0},{0,0,0,0}};
#pragma unroll
            for (int ks = 0; ks < 4; ks++) {
#pragma unroll
                for (int nt = 0; nt < 2; nt++) {
                    int sK = wc * 16 + nt * 8 + gid;
                    int d  = ks * 8 + tid4;
                    unsigned bb[2];
                    bb[0] = cvt_tf32(kbS[sK * 36 + d]);
                    bb[1] = cvt_tf32(kbS[sK * 36 + d + 4]);
                    mma_tf32(cS[nt], aS[ks], bb);
                    bb[0] = cvt_tf32(kbO[sK * 36 + d]);
                    bb[1] = cvt_tf32(kbO[sK * 36 + d + 4]);
                    mma_tf32(cO[nt], aO[ks], bb);
                }
            }

            // select + RMW into mask-prefilled score (single writer per cell)
#pragma unroll
            for (int nt = 0; nt < 2; nt++) {
                int scol = st * 128 + wc * 16 + nt * 8 + 2 * tid4;
                int ki0 = kid_s[scol], ki1 = kid_s[scol + 1];
#pragma unroll
                for (int r = 0; r < 4; r++) {
                    int row = wr * 16 + gid + ((r >> 1) << 3);
                    int col = scol + (r & 1);
                    int ki  = (r & 1) ? ki1 : ki0;
                    float val = (qid_s[row] == ki) ? cS[nt][r] : cO[nt][r];
                    score[row * SC_STR + col] += val;
                }
            }

            if (st < 7) {
                float* dstb = ktile + ((cur ^ 1) * 2) * 4608;
#pragma unroll
                for (int u = 0; u < 4; u++) {
                    int f = t + 512 * u;
                    int mat = f >> 10, r = (f >> 3) & 127, c4 = (f & 7) * 4;
                    *reinterpret_cast<float4*>(
                        &dstb[mat * 4608 + r * 36 + c4]) = kreg[u];
                }
            }
            __syncthreads();
        }

        // ================= softmax (warp w: rows 2w, 2w+1) ==================
#pragma unroll
        for (int rr = 0; rr < 2; rr++) {
            int row = 2 * w + rr;
            float4* pr = (float4*)(score + row * SC_STR);
            float mx = -CUDART_INF_F;
            for (int u = lane; u < 256; u += 32) {
                float4 x = pr[u];
                mx = fmaxf(mx, fmaxf(fmaxf(x.x, x.y), fmaxf(x.z, x.w)));
            }
#pragma unroll
            for (int o = 16; o > 0; o >>= 1)
                mx = fmaxf(mx, __shfl_xor_sync(0xffffffffu, mx, o));
            float s = 0.f;
            for (int u = lane; u < 256; u += 32) {
                float4 x = pr[u];
                x.x = fexp(x.x - mx); x.y = fexp(x.y - mx);
                x.z = fexp(x.z - mx); x.w = fexp(x.w - mx);
                s += (x.x + x.y) + (x.z + x.w);
                pr[u] = x;
            }
#pragma unroll
            for (int o = 16; o > 0; o >>= 1)
                s += __shfl_xor_sync(0xffffffffu, s, o);
            if (lane == 0) inv[row] = 1.0f / s;
        }
        __syncthreads();

        // ---- v prefetch tile 0 (overlaps attn-sum) ----
        float4 vreg[2];
#pragma unroll
        for (int u = 0; u < 2; u++) {
            int f = t + 512 * u;                  // 0..1023
            int r = f >> 3, c4 = (f & 7) * 4;
            vreg[u] = *reinterpret_cast<const float4*>(
                &g_vh[((size_t)(b * S_ + r)) * D_ + h * 32 + c4]);
        }

        // ---- attn-sum: accumulate p/H into gmem ----
        {
            float4* out4 = reinterpret_cast<float4*>(attn_out + mrow0);
#pragma unroll
            for (int u = 0; u < 16; u++) {
                int f = t + 512 * u;
                int row = f >> 8, c4g = f & 255;
                float sv = inv[row] * 0.125f;
                float4 ev = *reinterpret_cast<const float4*>(
                    &score[row * SC_STR + c4g * 4]);
                float4 o;
                if (h == 0) {
                    o.x = ev.x * sv; o.y = ev.y * sv;
                    o.z = ev.z * sv; o.w = ev.w * sv;
                } else {
                    float4 ov = out4[row * 256 + c4g];
                    o.x = fmaf(ev.x, sv, ov.x);
                    o.y = fmaf(ev.y, sv, ov.y);
                    o.z = fmaf(ev.z, sv, ov.z);
                    o.w = fmaf(ev.w, sv, ov.w);
                }
                out4[row * 256 + c4g] = o;
            }
        }

        // STS v tile 0 into vt buf0 (ktile region is dead now)
#pragma unroll
        for (int u = 0; u < 2; u++) {
            int f = t + 512 * u;
            int r = f >> 3, c4 = (f & 7) * 4;
            *reinterpret_cast<float4*>(&ktile[r * 40 + c4]) = vreg[u];
        }
        __syncthreads();

        // ================= PV phase (double-buffered v) =================
        float cv[4][4] = {{0,0,0,0},{0,0,0,0},{0,0,0,0},{0,0,0,0}};
        for (int st = 0; st < 8; st++) {
            const int cur = st & 1;
            if (st < 7) {
#pragma unroll
                for (int u = 0; u < 2; u++) {
                    int f = t + 512 * u;
                    int r = f >> 3, c4 = (f & 7) * 4;
                    vreg[u] = *reinterpret_cast<const float4*>(
                        &g_vh[((size_t)(b * S_ + (st + 1) * 128 + r)) * D_ +
                              h * 32 + c4]);
                }
            }
            const float* vt = ktile + cur * 5120;

#pragma unroll
            for (int i = 0; i < 2; i++) {
                int kl = wc * 16 + i * 8;          // s-offset within tile
                int sb = st * 128 + kl;
                unsigned av[4];
                av[0] = cvt_tf32(score[(wr * 16 + gid) * SC_STR + sb + tid4]);
                av[1] = cvt_tf32(score[(wr * 16 + gid + 8) * SC_STR + sb + tid4]);
                av[2] = cvt_tf32(score[(wr * 16 + gid) * SC_STR + sb + tid4 + 4]);
                av[3] = cvt_tf32(score[(wr * 16 + gid + 8) * SC_STR + sb + tid4 + 4]);
#pragma unroll
                for (int nt = 0; nt < 4; nt++) {
                    unsigned bv[2];
                    bv[0] = cvt_tf32(vt[(kl + tid4) * 40 + nt * 8 + gid]);
                    bv[1] = cvt_tf32(vt[(kl + tid4 + 4) * 40 + nt * 8 + gid]);
                    mma_tf32(cv[nt], av, bv);
                }
            }

            if (st < 7) {
                float* vdst = ktile + (cur ^ 1) * 5120;
#pragma unroll
                for (int u = 0; u < 2; u++) {
                    int f = t + 512 * u;
                    int r = f >> 3, c4 = (f & 7) * 4;
                    *reinterpret_cast<float4*>(&vdst[r * 40 + c4]) = vreg[u];
                }
            }
            __syncthreads();
        }

        // ---- partial C -> red (aliases score; all score reads are done) ----
#pragma unroll
        for (int nt = 0; nt < 4; nt++)
#pragma unroll
            for (int r = 0; r < 4; r++) {
                int rowl = wr * 16 + gid + ((r >> 1) << 3);
                int col  = nt * 8 + 2 * tid4 + (r & 1);
                red[wc * 1152 + rowl * 36 + col] = cv[nt][r];
            }
        __syncthreads();

        // ---- cross-chunk reduce + normalized ctx write ----
#pragma unroll
        for (int u = 0; u < 2; u++) {
            int e = t + 512 * u;                   // 0..1023
            int row = e >> 5, d = e & 31;
            float s = 0.f;
#pragma unroll
            for (int c = 0; c < 8; c++) s += red[c * 1152 + row * 36 + d];
            g_ctx[(qbase + row) * V_ + h * 32 + d] = s * inv[row];
        }
    }
}

// ---------------------------------------------------------------------------
extern "C" void kernel_launch(void* const* d_in, const int* in_sizes, int n_in,
                              void* d_out, int out_size)
{
    const float* q    = (const float*)d_in[0];
    const float* k    = (const float*)d_in[1];
    const float* v    = (const float*)d_in[2];
    const int*   qid  = (const int*)d_in[3];
    const int*   kid  = (const int*)d_in[4];
    const float* mask = (const float*)d_in[5];
    const float* wqs  = (const float*)d_in[6];
    const float* wqo  = (const float*)d_in[7];
    const float* wks  = (const float*)d_in[8];
    const float* wko  = (const float*)d_in[9];
    const float* wv   = (const float*)d_in[10];
    const float* fcw  = (const float*)d_in[11];
    const float* fcb  = (const float*)d_in[12];

    float* out      = (float*)d_out;
    float* attn_out = out + (size_t)B_ * L_ * V_;

    void *p_qs, *p_qo, *p_ks, *p_ko, *p_vh, *p_ctx;
    cudaGetSymbolAddress(&p_qs,  g_qs);
    cudaGetSymbolAddress(&p_qo,  g_qo);
    cudaGetSymbolAddress(&p_ks,  g_ks);
    cudaGetSymbolAddress(&p_ko,  g_ko);
    cudaGetSymbolAddress(&p_vh,  g_vh);
    cudaGetSymbolAddress(&p_ctx, g_ctx);

    cudaFuncSetAttribute(attn_kernel,
                         cudaFuncAttributeMaxDynamicSharedMemorySize,
                         AT_SMEM_BYTES);

    Proj5 p;
    p.A[0] = q;  p.W[0] = wqs; p.C[0] = (float*)p_qs; p.sc[0] = SCALE_F;
    p.A[1] = q;  p.W[1] = wqo; p.C[1] = (float*)p_qo; p.sc[1] = SCALE_F;
    p.A[2] = k;  p.W[2] = wks; p.C[2] = (float*)p_ks; p.sc[2] = 1.0f;
    p.A[3] = k;  p.W[3] = wko; p.C[3] = (float*)p_ko; p.sc[3] = 1.0f;
    p.A[4] = v;  p.W[4] = wv;  p.C[4] = (float*)p_vh; p.sc[4] = 1.0f;

    dim3 pgrid(V_ / 64, N_TOK / 128, 5);
    proj_kernel<<<pgrid, 256>>>(p);

    dim3 agrid(L_ / 32, B_);
    attn_kernel<<<agrid, 512, AT_SMEM_BYTES>>>(mask, qid, kid, attn_out);

    dim3 fgrid(V_ / 64, N_TOK / 128);
    fc_kernel<<<fgrid, 256>>>((const float*)p_ctx, fcw, fcb, out);
}

// round 6
// speedup vs baseline: 3.4444x; 1.0758x over previous
#include <cuda_runtime.h>
#include <math_constants.h>

#define B_  8
#define L_  1024
#define S_  1024
#define D_  256
#define V_  256
#define H_  8

#define N_TOK (B_*L_)
#define SCALE_F 0.17677669529663687f

// ---------------- scratch (static device arrays: allocation-free) ----------
__device__ float g_qs[N_TOK*D_];
__device__ float g_qo[N_TOK*D_];
__device__ float g_ks[N_TOK*D_];
__device__ float g_ko[N_TOK*D_];
__device__ float g_vh[N_TOK*D_];
__device__ float g_ctx[N_TOK*V_];

// ---------------- fast exp on FMA pipe (rel err ~2e-6) ---------------------
__device__ __forceinline__ float fexp(float x)
{
    float t = fmaxf(x * 1.4426950408889634f, -125.0f);
    float r = rintf(t);
    float f = t - r;
    float p = 1.3333558146428443e-3f;
    p = fmaf(p, f, 9.6181291076284772e-3f);
    p = fmaf(p, f, 5.5504108664821580e-2f);
    p = fmaf(p, f, 2.4022650695910071e-1f);
    p = fmaf(p, f, 6.9314718055994531e-1f);
    p = fmaf(p, f, 1.0f);
    return __int_as_float(__float_as_int(p) + (((int)r) << 23));
}

// ---------------- tf32 mma helpers -----------------------------------------
__device__ __forceinline__ unsigned cvt_tf32(float f)
{
    unsigned r;
    asm("cvt.rna.tf32.f32 %0, %1;" : "=r"(r) : "f"(f));
    return r;
}

__device__ __forceinline__ void mma_tf32(float c[4], const unsigned a[4],
                                         const unsigned b[2])
{
    asm("mma.sync.aligned.m16n8k8.row.col.f32.tf32.tf32.f32 "
        "{%0,%1,%2,%3}, {%4,%5,%6,%7}, {%8,%9}, {%0,%1,%2,%3};"
        : "+f"(c[0]), "+f"(c[1]), "+f"(c[2]), "+f"(c[3])
        : "r"(a[0]), "r"(a[1]), "r"(a[2]), "r"(a[3]),
          "r"(b[0]), "r"(b[1]));
}

// ---------------------------------------------------------------------------
// GEMM (fp32, reg double-buffer prefetch): C = scale*(A @ Bw^T) + bias.
// BM=128, BN=64, BK=16, 256 threads, 8x4 register tile.
// ---------------------------------------------------------------------------
__device__ __forceinline__ void gemm_body(
    const float* __restrict__ A, const float* __restrict__ Bw,
    float* __restrict__ C, int N, int K,
    float scale, const float* __restrict__ bias)
{
    const int BM = 128, BN = 64, BK = 16;
    __shared__ __align__(16) float As[BK][BM + 4];
    __shared__ __align__(16) float Bs[BK][BN + 4];

    int t  = threadIdx.x;
    int m0 = blockIdx.y * BM;
    int n0 = blockIdx.x * BN;
    int tx = t & 15;
    int ty = t >> 4;

    float acc[8][4];
#pragma unroll
    for (int i = 0; i < 8; i++)
#pragma unroll
        for (int j = 0; j < 4; j++) acc[i][j] = 0.f;

    const int ra = t >> 2;            // 0..63
    const int ca = (t & 3) * 4;       // 0,4,8,12

    // prefetch tile 0
    float4 pa0 = *reinterpret_cast<const float4*>(&A[(size_t)(m0 + ra) * K + ca]);
    float4 pa1 = *reinterpret_cast<const float4*>(&A[(size_t)(m0 + ra + 64) * K + ca]);
    float4 pb  = *reinterpret_cast<const float4*>(&Bw[(size_t)(n0 + ra) * K + ca]);

    for (int k0 = 0; k0 < K; k0 += BK) {
        As[ca + 0][ra] = pa0.x;  As[ca + 1][ra] = pa0.y;
        As[ca + 2][ra] = pa0.z;  As[ca + 3][ra] = pa0.w;
        As[ca + 0][ra + 64] = pa1.x;  As[ca + 1][ra + 64] = pa1.y;
        As[ca + 2][ra + 64] = pa1.z;  As[ca + 3][ra + 64] = pa1.w;
        Bs[ca + 0][ra] = pb.x;   Bs[ca + 1][ra] = pb.y;
        Bs[ca + 2][ra] = pb.z;   Bs[ca + 3][ra] = pb.w;
        __syncthreads();

        if (k0 + BK < K) {
            int c = k0 + BK + ca;
            pa0 = *reinterpret_cast<const float4*>(&A[(size_t)(m0 + ra) * K + c]);
            pa1 = *reinterpret_cast<const float4*>(&A[(size_t)(m0 + ra + 64) * K + c]);
            pb  = *reinterpret_cast<const float4*>(&Bw[(size_t)(n0 + ra) * K + c]);
        }

#pragma unroll
        for (int k = 0; k < BK; k++) {
            float4 a0 = *reinterpret_cast<const float4*>(&As[k][ty * 8]);
            float4 a1 = *reinterpret_cast<const float4*>(&As[k][ty * 8 + 4]);
            float4 b0 = *reinterpret_cast<const float4*>(&Bs[k][tx * 4]);
            float a[8] = {a0.x, a0.y, a0.z, a0.w, a1.x, a1.y, a1.z, a1.w};
            float bb[4] = {b0.x, b0.y, b0.z, b0.w};
#pragma unroll
            for (int i = 0; i < 8; i++)
#pragma unroll
                for (int j = 0; j < 4; j++) acc[i][j] += a[i] * bb[j];
        }
        __syncthreads();
    }

    float bv[4] = {0.f, 0.f, 0.f, 0.f};
    if (bias) {
#pragma unroll
        for (int j = 0; j < 4; j++) bv[j] = bias[n0 + tx * 4 + j];
    }
#pragma unroll
    for (int i = 0; i < 8; i++) {
        int row = m0 + ty * 8 + i;
        float4 o;
        o.x = acc[i][0] * scale + bv[0];
        o.y = acc[i][1] * scale + bv[1];
        o.z = acc[i][2] * scale + bv[2];
        o.w = acc[i][3] * scale + bv[3];
        *reinterpret_cast<float4*>(&C[(size_t)row * N + n0 + tx * 4]) = o;
    }
}

struct Proj5 {
    const float* A[5];
    const float* W[5];
    float*       C[5];
    float        sc[5];
};

__global__ __launch_bounds__(256, 3)
void proj_kernel(Proj5 p)
{
    int z = blockIdx.z;
    gemm_body(p.A[z], p.W[z], p.C[z], D_, D_, p.sc[z], nullptr);
}

__global__ __launch_bounds__(256, 3)
void fc_kernel(const float* __restrict__ A, const float* __restrict__ W,
               const float* __restrict__ bias, float* __restrict__ C)
{
    gemm_body(A, W, C, V_, V_, 1.0f, bias);
}

// ---------------------------------------------------------------------------
// Attention (tf32 mma): block = (b, 32 l-rows), 512 threads, 1 block/SM.
// smem floats:
//   score [32][1036] = 33152  (aliased by red[8][32][36] after PV)
//   ktile 2buf x 2mat x [128][36] = 18432  (aliased by vt 2buf x [128][40])
//   inv 32 | qid 32(int) | kid 1024(int)
// ---------------------------------------------------------------------------
#define SC_STR 1036
#define AT_SMEM_BYTES ((33152 + 18432 + 32 + 32 + 1024) * 4)

__global__ __launch_bounds__(512, 1)
void attn_kernel(const float* __restrict__ mask,
                 const int* __restrict__ qid,
                 const int* __restrict__ kid,
                 float* __restrict__ attn_out)
{
    extern __shared__ float sm[];
    float* score = sm;                        // [32][1036]
    float* ktile = sm + 32 * SC_STR;          // 2x2x[128][36]
    float* red   = sm;                        // alias: [8][32][36] (PV reduce)
    float* inv   = ktile + 18432;             // [32]
    int*   qid_s = (int*)(inv + 32);          // [32]
    int*   kid_s = qid_s + 32;                // [1024]

    const int b    = blockIdx.y;
    const int l0   = blockIdx.x * 32;
    const int t    = threadIdx.x;
    const int lane = t & 31;
    const int w    = t >> 5;                  // 0..15
    const int gid  = lane >> 2;
    const int tid4 = lane & 3;
    const int wr   = w & 1;                   // row m16-tile
    const int wc   = w >> 1;                  // 16-col group / PV s-chunk

    const size_t qbase = (size_t)(b * L_ + l0);
    const size_t mrow0 = qbase * S_;

    for (int i = t; i < S_; i += 512) kid_s[i] = kid[b * S_ + i];
    if (t < 32) qid_s[t] = qid[b * L_ + l0 + t];

    for (int h = 0; h < H_; h++) {
        __syncthreads();   // prev head fully done; ids visible (h=0)

        // ---- A fragments (q self/other) straight from gmem ----
        unsigned aS[4][4], aO[4][4];
        {
            const size_t r0 = (qbase + wr * 16 + gid) * D_;
            const size_t r1 = (qbase + wr * 16 + gid + 8) * D_;
#pragma unroll
            for (int ks = 0; ks < 4; ks++) {
                int kk = h * 32 + ks * 8 + tid4;
                aS[ks][0] = cvt_tf32(g_qs[r0 + kk]);
                aS[ks][1] = cvt_tf32(g_qs[r1 + kk]);
                aS[ks][2] = cvt_tf32(g_qs[r0 + kk + 4]);
                aS[ks][3] = cvt_tf32(g_qs[r1 + kk + 4]);
                aO[ks][0] = cvt_tf32(g_qo[r0 + kk]);
                aO[ks][1] = cvt_tf32(g_qo[r1 + kk]);
                aO[ks][2] = cvt_tf32(g_qo[r0 + kk + 4]);
                aO[ks][3] = cvt_tf32(g_qo[r1 + kk + 4]);
            }
        }

        // ---- k prefetch tile 0 ----
        float4 kreg[4];
#pragma unroll
        for (int u = 0; u < 4; u++) {
            int f = t + 512 * u;                  // 0..2047
            int mat = f >> 10, r = (f >> 3) & 127, c4 = (f & 7) * 4;
            const float* src = mat ? g_ko : g_ks;
            kreg[u] = *reinterpret_cast<const float4*>(
                &src[((size_t)(b * S_ + r)) * D_ + h * 32 + c4]);
        }
#pragma unroll
        for (int u = 0; u < 4; u++) {
            int f = t + 512 * u;
            int mat = f >> 10, r = (f >> 3) & 127, c4 = (f & 7) * 4;
            *reinterpret_cast<float4*>(&ktile[mat * 4608 + r * 36 + c4]) = kreg[u];
        }
        __syncthreads();

        // ================= score phase (double-buffered k) =================
        for (int st = 0; st < 8; st++) {
            const int cur = st & 1;
            if (st < 7) {
#pragma unroll
                for (int u = 0; u < 4; u++) {
                    int f = t + 512 * u;
                    int mat = f >> 10, r = (f >> 3) & 127, c4 = (f & 7) * 4;
                    const float* src = mat ? g_ko : g_ks;
                    kreg[u] = *reinterpret_cast<const float4*>(
                        &src[((size_t)(b * S_ + (st + 1) * 128 + r)) * D_ +
                             h * 32 + c4]);
                }
            }

            // mask fragments for this tile (in flight under MMAs)
            float2 mfr[2][2];
#pragma unroll
            for (int nt = 0; nt < 2; nt++) {
                int scol = st * 128 + wc * 16 + nt * 8 + 2 * tid4;
#pragma unroll
                for (int rp = 0; rp < 2; rp++) {
                    int row = wr * 16 + gid + 8 * rp;
                    mfr[nt][rp] = *reinterpret_cast<const float2*>(
                        &mask[mrow0 + (size_t)row * S_ + scol]);
                }
            }

            const float* kbS = ktile + (cur * 2 + 0) * 4608;
            const float* kbO = ktile + (cur * 2 + 1) * 4608;

            float cS[2][4] = {{0,0,0,0},{0,0,0,0}};
            float cO[2][4] = {{0,0,0,0},{0,0,0,0}};
#pragma unroll
            for (int ks = 0; ks < 4; ks++) {
#pragma unroll
                for (int nt = 0; nt < 2; nt++) {
                    int sK = wc * 16 + nt * 8 + gid;
                    int d  = ks * 8 + tid4;
                    unsigned bb[2];
                    bb[0] = cvt_tf32(kbS[sK * 36 + d]);
                    bb[1] = cvt_tf32(kbS[sK * 36 + d + 4]);
                    mma_tf32(cS[nt], aS[ks], bb);
                    bb[0] = cvt_tf32(kbO[sK * 36 + d]);
                    bb[1] = cvt_tf32(kbO[sK * 36 + d + 4]);
                    mma_tf32(cO[nt], aO[ks], bb);
                }
            }

            // select + add mask + single STS.64 per fragment pair
#pragma unroll
            for (int nt = 0; nt < 2; nt++) {
                int scol = st * 128 + wc * 16 + nt * 8 + 2 * tid4;
                int ki0 = kid_s[scol], ki1 = kid_s[scol + 1];
#pragma unroll
                for (int rp = 0; rp < 2; rp++) {
                    int row = wr * 16 + gid + 8 * rp;
                    int qi  = qid_s[row];
                    float v0 = ((qi == ki0) ? cS[nt][2*rp]   : cO[nt][2*rp])   + mfr[nt][rp].x;
                    float v1 = ((qi == ki1) ? cS[nt][2*rp+1] : cO[nt][2*rp+1]) + mfr[nt][rp].y;
                    *reinterpret_cast<float2*>(&score[row * SC_STR + scol]) =
                        make_float2(v0, v1);
                }
            }

            if (st < 7) {
                float* dstb = ktile + ((cur ^ 1) * 2) * 4608;
#pragma unroll
                for (int u = 0; u < 4; u++) {
                    int f = t + 512 * u;
                    int mat = f >> 10, r = (f >> 3) & 127, c4 = (f & 7) * 4;
                    *reinterpret_cast<float4*>(
                        &dstb[mat * 4608 + r * 36 + c4]) = kreg[u];
                }
            }
            __syncthreads();
        }

        // ---- v prefetch tile 0 (in flight during softmax) ----
        float4 vreg[2];
#pragma unroll
        for (int u = 0; u < 2; u++) {
            int f = t + 512 * u;                  // 0..1023
            int r = f >> 3, c4 = (f & 7) * 4;
            vreg[u] = *reinterpret_cast<const float4*>(
                &g_vh[((size_t)(b * S_ + r)) * D_ + h * 32 + c4]);
        }

        // ======= softmax + folded attn-sum (warp w: rows 2w, 2w+1) =========
#pragma unroll
        for (int rr = 0; rr < 2; rr++) {
            int row = 2 * w + rr;
            float4* pr = (float4*)(score + row * SC_STR);
            float mx = -CUDART_INF_F;
#pragma unroll
            for (int u8 = 0; u8 < 8; u8++) {
                float4 x = pr[lane + 32 * u8];
                mx = fmaxf(mx, fmaxf(fmaxf(x.x, x.y), fmaxf(x.z, x.w)));
            }
#pragma unroll
            for (int o = 16; o > 0; o >>= 1)
                mx = fmaxf(mx, __shfl_xor_sync(0xffffffffu, mx, o));
            float s = 0.f;
#pragma unroll
            for (int u8 = 0; u8 < 8; u8++) {
                float4 x = pr[lane + 32 * u8];
                x.x = fexp(x.x - mx); x.y = fexp(x.y - mx);
                x.z = fexp(x.z - mx); x.w = fexp(x.w - mx);
                s += (x.x + x.y) + (x.z + x.w);
                pr[lane + 32 * u8] = x;
            }
#pragma unroll
            for (int o = 16; o > 0; o >>= 1)
                s += __shfl_xor_sync(0xffffffffu, s, o);
            float iv = 1.0f / s;
            if (lane == 0) inv[row] = iv;

            // attn-sum RMW for this row (owner warp, coalesced)
            float sv = iv * 0.125f;
            float4* out4 = reinterpret_cast<float4*>(
                attn_out + mrow0 + (size_t)row * S_);
#pragma unroll
            for (int u8 = 0; u8 < 8; u8++) {
                int u = lane + 32 * u8;
                float4 ev = pr[u];
                float4 o;
                if (h == 0) {
                    o.x = ev.x * sv; o.y = ev.y * sv;
                    o.z = ev.z * sv; o.w = ev.w * sv;
                } else {
                    float4 ov = out4[u];
                    o.x = fmaf(ev.x, sv, ov.x);
                    o.y = fmaf(ev.y, sv, ov.y);
                    o.z = fmaf(ev.z, sv, ov.z);
                    o.w = fmaf(ev.w, sv, ov.w);
                }
                out4[u] = o;
            }
        }

        // STS v tile 0 into vt buf0 (ktile dead; peers' ktile reads synced)
#pragma unroll
        for (int u = 0; u < 2; u++) {
            int f = t + 512 * u;
            int r = f >> 3, c4 = (f & 7) * 4;
            *reinterpret_cast<float4*>(&ktile[r * 40 + c4]) = vreg[u];
        }
        __syncthreads();

        // ================= PV phase (double-buffered v) =================
        float cv[4][4] = {{0,0,0,0},{0,0,0,0},{0,0,0,0},{0,0,0,0}};
        for (int st = 0; st < 8; st++) {
            const int cur = st & 1;
            if (st < 7) {
#pragma unroll
                for (int u = 0; u < 2; u++) {
                    int f = t + 512 * u;
                    int r = f >> 3, c4 = (f & 7) * 4;
                    vreg[u] = *reinterpret_cast<const float4*>(
                        &g_vh[((size_t)(b * S_ + (st + 1) * 128 + r)) * D_ +
                              h * 32 + c4]);
                }
            }
            const float* vt = ktile + cur * 5120;

#pragma unroll
            for (int i = 0; i < 2; i++) {
                int kl = wc * 16 + i * 8;
                int sb = st * 128 + kl;
                unsigned av[4];
                av[0] = cvt_tf32(score[(wr * 16 + gid) * SC_STR + sb + tid4]);
                av[1] = cvt_tf32(score[(wr * 16 + gid + 8) * SC_STR + sb + tid4]);
                av[2] = cvt_tf32(score[(wr * 16 + gid) * SC_STR + sb + tid4 + 4]);
                av[3] = cvt_tf32(score[(wr * 16 + gid + 8) * SC_STR + sb + tid4 + 4]);
#pragma unroll
                for (int nt = 0; nt < 4; nt++) {
                    unsigned bv[2];
                    bv[0] = cvt_tf32(vt[(kl + tid4) * 40 + nt * 8 + gid]);
                    bv[1] = cvt_tf32(vt[(kl + tid4 + 4) * 40 + nt * 8 + gid]);
                    mma_tf32(cv[nt], av, bv);
                }
            }

            if (st < 7) {
                float* vdst = ktile + (cur ^ 1) * 5120;
#pragma unroll
                for (int u = 0; u < 2; u++) {
                    int f = t + 512 * u;
                    int r = f >> 3, c4 = (f & 7) * 4;
                    *reinterpret_cast<float4*>(&vdst[r * 40 + c4]) = vreg[u];
                }
            }
            __syncthreads();
        }

        // ---- partial C -> red (aliases score; all score reads done) ----
#pragma unroll
        for (int nt = 0; nt < 4; nt++)
#pragma unroll
            for (int r = 0; r < 4; r++) {
                int rowl = wr * 16 + gid + ((r >> 1) << 3);
                int col  = nt * 8 + 2 * tid4 + (r & 1);
                red[wc * 1152 + rowl * 36 + col] = cv[nt][r];
            }
        __syncthreads();

        // ---- cross-chunk reduce + normalized ctx write ----
#pragma unroll
        for (int u = 0; u < 2; u++) {
            int e = t + 512 * u;                   // 0..1023
            int row = e >> 5, d = e & 31;
            float s = 0.f;
#pragma unroll
            for (int c = 0; c < 8; c++) s += red[c * 1152 + row * 36 + d];
            g_ctx[(qbase + row) * V_ + h * 32 + d] = s * inv[row];
        }
    }
}

// ---------------------------------------------------------------------------
extern "C" void kernel_launch(void* const* d_in, const int* in_sizes, int n_in,
                              void* d_out, int out_size)
{
    const float* q    = (const float*)d_in[0];
    const float* k    = (const float*)d_in[1];
    const float* v    = (const float*)d_in[2];
    const int*   qid  = (const int*)d_in[3];
    const int*   kid  = (const int*)d_in[4];
    const float* mask = (const float*)d_in[5];
    const float* wqs  = (const float*)d_in[6];
    const float* wqo  = (const float*)d_in[7];
    const float* wks  = (const float*)d_in[8];
    const float* wko  = (const float*)d_in[9];
    const float* wv   = (const float*)d_in[10];
    const float* fcw  = (const float*)d_in[11];
    const float* fcb  = (const float*)d_in[12];

    float* out      = (float*)d_out;
    float* attn_out = out + (size_t)B_ * L_ * V_;

    void *p_qs, *p_qo, *p_ks, *p_ko, *p_vh, *p_ctx;
    cudaGetSymbolAddress(&p_qs,  g_qs);
    cudaGetSymbolAddress(&p_qo,  g_qo);
    cudaGetSymbolAddress(&p_ks,  g_ks);
    cudaGetSymbolAddress(&p_ko,  g_ko);
    cudaGetSymbolAddress(&p_vh,  g_vh);
    cudaGetSymbolAddress(&p_ctx, g_ctx);

    cudaFuncSetAttribute(attn_kernel,
                         cudaFuncAttributeMaxDynamicSharedMemorySize,
                         AT_SMEM_BYTES);

    Proj5 p;
    p.A[0] = q;  p.W[0] = wqs; p.C[0] = (float*)p_qs; p.sc[0] = SCALE_F;
    p.A[1] = q;  p.W[1] = wqo; p.C[1] = (float*)p_qo; p.sc[1] = SCALE_F;
    p.A[2] = k;  p.W[2] = wks; p.C[2] = (float*)p_ks; p.sc[2] = 1.0f;
    p.A[3] = k;  p.W[3] = wko; p.C[3] = (float*)p_ko; p.sc[3] = 1.0f;
    p.A[4] = v;  p.W[4] = wv;  p.C[4] = (float*)p_vh; p.sc[4] = 1.0f;

    dim3 pgrid(V_ / 64, N_TOK / 128, 5);
    proj_kernel<<<pgrid, 256>>>(p);

    dim3 agrid(L_ / 32, B_);
    attn_kernel<<<agrid, 512, AT_SMEM_BYTES>>>(mask, qid, kid, attn_out);

    dim3 fgrid(V_ / 64, N_TOK / 128);
    fc_kernel<<<fgrid, 256>>>((const float*)p_ctx, fcw, fcb, out);
}

// round 7
// speedup vs baseline: 3.6281x; 1.0533x over previous
#include <cuda_runtime.h>
#include <math_constants.h>

#define B_  8
#define L_  1024
#define S_  1024
#define D_  256
#define V_  256
#define H_  8

#define N_TOK (B_*L_)
#define SCALE_F 0.17677669529663687f

// ---------------- scratch (static device arrays: allocation-free) ----------
// g_qs/g_qo/g_ks/g_ko: tf32 bits, row-major tokens, d-permuted so (d,d+4)
//   are adjacent:  pos = h*32 + 2*p + hi,  p = (dd>>3)*4 + (dd&3), hi=(dd>>2)&1
// g_vh: tf32 bits, blocked [b][sblk=s/8][h][col=32][8] with inner
//   (s%4)*2 + (s%8)/4  -> (s, s+4) adjacent
__device__ float g_qs[N_TOK*D_];
__device__ float g_qo[N_TOK*D_];
__device__ float g_ks[N_TOK*D_];
__device__ float g_ko[N_TOK*D_];
__device__ float g_vh[N_TOK*D_];
__device__ float g_ctx[N_TOK*V_];

// ---------------- fast exp on FMA pipe (rel err ~2e-6) ---------------------
__device__ __forceinline__ float fexp(float x)
{
    float t = fmaxf(x * 1.4426950408889634f, -125.0f);
    float r = rintf(t);
    float f = t - r;
    float p = 1.3333558146428443e-3f;
    p = fmaf(p, f, 9.6181291076284772e-3f);
    p = fmaf(p, f, 5.5504108664821580e-2f);
    p = fmaf(p, f, 2.4022650695910071e-1f);
    p = fmaf(p, f, 6.9314718055994531e-1f);
    p = fmaf(p, f, 1.0f);
    return __int_as_float(__float_as_int(p) + (((int)r) << 23));
}

// ---------------- tf32 mma helpers -----------------------------------------
__device__ __forceinline__ unsigned cvt_tf32(float f)
{
    unsigned r;
    asm("cvt.rna.tf32.f32 %0, %1;" : "=r"(r) : "f"(f));
    return r;
}

__device__ __forceinline__ void mma_tf32(float c[4], const unsigned a[4],
                                         const unsigned b[2])
{
    asm("mma.sync.aligned.m16n8k8.row.col.f32.tf32.tf32.f32 "
        "{%0,%1,%2,%3}, {%4,%5,%6,%7}, {%8,%9}, {%0,%1,%2,%3};"
        : "+f"(c[0]), "+f"(c[1]), "+f"(c[2]), "+f"(c[3])
        : "r"(a[0]), "r"(a[1]), "r"(a[2]), "r"(a[3]),
          "r"(b[0]), "r"(b[1]));
}

// ---------------------------------------------------------------------------
// GEMM (fp32, reg double-buffer prefetch): C = scale*(A @ Bw^T) + bias.
// mode 0: plain fp32 row-major (+bias)
// mode 1: tf32, d-pair permuted row-major (q/k scratch)
// mode 2: tf32, s-pair blocked layout (v scratch)
// ---------------------------------------------------------------------------
__device__ __forceinline__ void gemm_body(
    const float* __restrict__ A, const float* __restrict__ Bw,
    float* __restrict__ C, int N, int K,
    float scale, const float* __restrict__ bias, int mode)
{
    const int BM = 128, BN = 64, BK = 16;
    __shared__ __align__(16) float As[BK][BM + 4];
    __shared__ __align__(16) float Bs[BK][BN + 4];

    int t  = threadIdx.x;
    int m0 = blockIdx.y * BM;
    int n0 = blockIdx.x * BN;
    int tx = t & 15;
    int ty = t >> 4;

    float acc[8][4];
#pragma unroll
    for (int i = 0; i < 8; i++)
#pragma unroll
        for (int j = 0; j < 4; j++) acc[i][j] = 0.f;

    const int ra = t >> 2;
    const int ca = (t & 3) * 4;

    float4 pa0 = *reinterpret_cast<const float4*>(&A[(size_t)(m0 + ra) * K + ca]);
    float4 pa1 = *reinterpret_cast<const float4*>(&A[(size_t)(m0 + ra + 64) * K + ca]);
    float4 pb  = *reinterpret_cast<const float4*>(&Bw[(size_t)(n0 + ra) * K + ca]);

    for (int k0 = 0; k0 < K; k0 += BK) {
        As[ca + 0][ra] = pa0.x;  As[ca + 1][ra] = pa0.y;
        As[ca + 2][ra] = pa0.z;  As[ca + 3][ra] = pa0.w;
        As[ca + 0][ra + 64] = pa1.x;  As[ca + 1][ra + 64] = pa1.y;
        As[ca + 2][ra + 64] = pa1.z;  As[ca + 3][ra + 64] = pa1.w;
        Bs[ca + 0][ra] = pb.x;   Bs[ca + 1][ra] = pb.y;
        Bs[ca + 2][ra] = pb.z;   Bs[ca + 3][ra] = pb.w;
        __syncthreads();

        if (k0 + BK < K) {
            int c = k0 + BK + ca;
            pa0 = *reinterpret_cast<const float4*>(&A[(size_t)(m0 + ra) * K + c]);
            pa1 = *reinterpret_cast<const float4*>(&A[(size_t)(m0 + ra + 64) * K + c]);
            pb  = *reinterpret_cast<const float4*>(&Bw[(size_t)(n0 + ra) * K + c]);
        }

#pragma unroll
        for (int k = 0; k < BK; k++) {
            float4 a0 = *reinterpret_cast<const float4*>(&As[k][ty * 8]);
            float4 a1 = *reinterpret_cast<const float4*>(&As[k][ty * 8 + 4]);
            float4 b0 = *reinterpret_cast<const float4*>(&Bs[k][tx * 4]);
            float a[8] = {a0.x, a0.y, a0.z, a0.w, a1.x, a1.y, a1.z, a1.w};
            float bb[4] = {b0.x, b0.y, b0.z, b0.w};
#pragma unroll
            for (int i = 0; i < 8; i++)
#pragma unroll
                for (int j = 0; j < 4; j++) acc[i][j] += a[i] * bb[j];
        }
        __syncthreads();
    }

    if (mode == 0) {
        float bv[4] = {0.f, 0.f, 0.f, 0.f};
        if (bias) {
#pragma unroll
            for (int j = 0; j < 4; j++) bv[j] = bias[n0 + tx * 4 + j];
        }
#pragma unroll
        for (int i = 0; i < 8; i++) {
            int row = m0 + ty * 8 + i;
            float4 o;
            o.x = acc[i][0] * scale + bv[0];
            o.y = acc[i][1] * scale + bv[1];
            o.z = acc[i][2] * scale + bv[2];
            o.w = acc[i][3] * scale + bv[3];
            *reinterpret_cast<float4*>(&C[(size_t)row * N + n0 + tx * 4]) = o;
        }
    } else if (mode == 1) {
        // tf32, d-pair permuted row-major
#pragma unroll
        for (int i = 0; i < 8; i++) {
            int row = m0 + ty * 8 + i;
#pragma unroll
            for (int j = 0; j < 4; j++) {
                int n  = n0 + tx * 4 + j;
                int hh = n >> 5, dd = n & 31;
                int p  = ((dd >> 3) << 2) | (dd & 3);
                int pos = (hh << 5) + 2 * p + ((dd >> 2) & 1);
                C[(size_t)row * D_ + pos] =
                    __uint_as_float(cvt_tf32(acc[i][j] * scale));
            }
        }
    } else {
        // tf32, v blocked layout: [b][sblk][h][col][8]
#pragma unroll
        for (int i = 0; i < 4; i++) {
            int row  = m0 + ty * 8 + i;
            int bb2  = row >> 10;
            int s    = row & 1023;
            int sblk = s >> 3;
#pragma unroll
            for (int j = 0; j < 4; j++) {
                int n  = n0 + tx * 4 + j;
                int hh = n >> 5, col = n & 31;
                size_t idx = (((size_t)(bb2 * 128 + sblk) * 8 + hh)) * 256 +
                             col * 8 + i * 2;
                float2 o;
                o.x = __uint_as_float(cvt_tf32(acc[i][j]));
                o.y = __uint_as_float(cvt_tf32(acc[i + 4][j]));
                *reinterpret_cast<float2*>(&C[idx]) = o;
            }
        }
    }
}

struct Proj5 {
    const float* A[5];
    const float* W[5];
    float*       C[5];
    float        sc[5];
    int          md[5];
};

__global__ __launch_bounds__(256, 3)
void proj_kernel(Proj5 p)
{
    int z = blockIdx.z;
    gemm_body(p.A[z], p.W[z], p.C[z], D_, D_, p.sc[z], nullptr, p.md[z]);
}

__global__ __launch_bounds__(256, 3)
void fc_kernel(const float* __restrict__ A, const float* __restrict__ W,
               const float* __restrict__ bias, float* __restrict__ C)
{
    gemm_body(A, W, C, V_, V_, 1.0f, bias, 0);
}

// ---------------------------------------------------------------------------
// Attention (tf32 mma, barrier-light): block = (b, 32 l-rows), 512 thr, 1/SM.
// All MMA operands (q,k,v) stream as LDG.64 fragments from L2-resident,
// pre-permuted tf32 scratch. 4 barriers per head.
// smem floats: score [32][1036] | red [4][32][36] | inv 32 | qid 32 | kid 1024
// ---------------------------------------------------------------------------
#define SC_STR 1036
#define AT_SMEM_BYTES ((32*SC_STR + 4608 + 32 + 32 + 1024) * 4)

__global__ __launch_bounds__(512, 1)
void attn_kernel(const float* __restrict__ mask,
                 const int* __restrict__ qid,
                 const int* __restrict__ kid,
                 float* __restrict__ attn_out)
{
    extern __shared__ float sm[];
    float* score = sm;                        // [32][1036]
    float* red   = sm + 32 * SC_STR;          // [4][32][36]
    float* inv   = red + 4608;                // [32]
    int*   qid_s = (int*)(inv + 32);          // [32]
    int*   kid_s = qid_s + 32;                // [1024]

    const int b    = blockIdx.y;
    const int l0   = blockIdx.x * 32;
    const int t    = threadIdx.x;
    const int lane = t & 31;
    const int w    = t >> 5;                  // 0..15
    const int gid  = lane >> 2;
    const int tid4 = lane & 3;

    const size_t qbase = (size_t)(b * L_ + l0);   // token base (q rows)
    const size_t kbase = (size_t)(b * S_);        // token base (k rows)
    const size_t mrow0 = qbase * S_;

    // score-phase: warp w owns cols w*64 .. w*64+63, all 32 rows
    const int cb = w * 64;
    // PV: warp = (nc, sh): cols nc*8, s-quarter sh*256
    const int nc = w & 3;
    const int sh = w >> 2;

    for (int i = t; i < S_; i += 512) kid_s[i] = kid[b * S_ + i];
    if (t < 32) qid_s[t] = qid[b * L_ + l0 + t];

    for (int h = 0; h < H_; h++) {
        __syncthreads();   // prev head fully done; ids visible (h=0)

        // ---- A fragments (q self/other): LDG.64 pairs, already tf32 ----
        unsigned aS[2][4][4], aO[2][4][4];
#pragma unroll
        for (int rt = 0; rt < 2; rt++) {
            const size_t r0 = (qbase + rt * 16 + gid) * D_ + h * 32;
            const size_t r1 = (qbase + rt * 16 + gid + 8) * D_ + h * 32;
#pragma unroll
            for (int ks = 0; ks < 4; ks++) {
                int off = 2 * (ks * 4 + tid4);
                uint2 lo = *reinterpret_cast<const uint2*>(&g_qs[r0 + off]);
                uint2 hi = *reinterpret_cast<const uint2*>(&g_qs[r1 + off]);
                aS[rt][ks][0] = lo.x; aS[rt][ks][1] = hi.x;
                aS[rt][ks][2] = lo.y; aS[rt][ks][3] = hi.y;
                lo = *reinterpret_cast<const uint2*>(&g_qo[r0 + off]);
                hi = *reinterpret_cast<const uint2*>(&g_qo[r1 + off]);
                aO[rt][ks][0] = lo.x; aO[rt][ks][1] = hi.x;
                aO[rt][ks][2] = lo.y; aO[rt][ks][3] = hi.y;
            }
        }

        int qi[2][2];
#pragma unroll
        for (int rt = 0; rt < 2; rt++) {
            qi[rt][0] = qid_s[rt * 16 + gid];
            qi[rt][1] = qid_s[rt * 16 + gid + 8];
        }

        // ================= score phase (no barriers) =================
#pragma unroll 2
        for (int nt = 0; nt < 8; nt++) {
            const int sK   = cb + nt * 8 + gid;          // this lane's B col
            const int scol = cb + nt * 8 + 2 * tid4;     // this lane's C cols

            // B fragments: LDG.64 from permuted tf32 k scratch
            unsigned bS[4][2], bO[4][2];
            const size_t krow = (kbase + sK) * D_ + h * 32;
#pragma unroll
            for (int ks = 0; ks < 4; ks++) {
                int off = 2 * (ks * 4 + tid4);
                uint2 v = *reinterpret_cast<const uint2*>(&g_ks[krow + off]);
                bS[ks][0] = v.x; bS[ks][1] = v.y;
                v = *reinterpret_cast<const uint2*>(&g_ko[krow + off]);
                bO[ks][0] = v.x; bO[ks][1] = v.y;
            }

            // mask fragments + kid (in flight under MMAs)
            int2 ki = *reinterpret_cast<const int2*>(&kid_s[scol]);
            float2 mf[2][2];
#pragma unroll
            for (int rt = 0; rt < 2; rt++)
#pragma unroll
                for (int rp = 0; rp < 2; rp++) {
                    int row = rt * 16 + gid + 8 * rp;
                    mf[rt][rp] = *reinterpret_cast<const float2*>(
                        &mask[mrow0 + (size_t)row * S_ + scol]);
                }

            float cS[2][4] = {{0,0,0,0},{0,0,0,0}};
            float cO[2][4] = {{0,0,0,0},{0,0,0,0}};
#pragma unroll
            for (int ks = 0; ks < 4; ks++) {
#pragma unroll
                for (int rt = 0; rt < 2; rt++) {
                    mma_tf32(cS[rt], aS[rt][ks], bS[ks]);
                    mma_tf32(cO[rt], aO[rt][ks], bO[ks]);
                }
            }

            // select + mask + STS.64
#pragma unroll
            for (int rt = 0; rt < 2; rt++)
#pragma unroll
                for (int rp = 0; rp < 2; rp++) {
                    int row = rt * 16 + gid + 8 * rp;
                    float v0 = ((qi[rt][rp] == ki.x) ? cS[rt][2*rp]   : cO[rt][2*rp])   + mf[rt][rp].x;
                    float v1 = ((qi[rt][rp] == ki.y) ? cS[rt][2*rp+1] : cO[rt][2*rp+1]) + mf[rt][rp].y;
                    *reinterpret_cast<float2*>(&score[row * SC_STR + scol]) =
                        make_float2(v0, v1);
                }
        }
        __syncthreads();

        // ======= softmax + folded attn-sum (warp w: rows 2w, 2w+1) =========
#pragma unroll
        for (int rr = 0; rr < 2; rr++) {
            int row = 2 * w + rr;
            float4* pr = (float4*)(score + row * SC_STR);
            float mx = -CUDART_INF_F;
#pragma unroll
            for (int u8 = 0; u8 < 8; u8++) {
                float4 x = pr[lane + 32 * u8];
                mx = fmaxf(mx, fmaxf(fmaxf(x.x, x.y), fmaxf(x.z, x.w)));
            }
#pragma unroll
            for (int o = 16; o > 0; o >>= 1)
                mx = fmaxf(mx, __shfl_xor_sync(0xffffffffu, mx, o));
            float s = 0.f;
#pragma unroll
            for (int u8 = 0; u8 < 8; u8++) {
                float4 x = pr[lane + 32 * u8];
                x.x = fexp(x.x - mx); x.y = fexp(x.y - mx);
                x.z = fexp(x.z - mx); x.w = fexp(x.w - mx);
                s += (x.x + x.y) + (x.z + x.w);
                pr[lane + 32 * u8] = x;
            }
#pragma unroll
            for (int o = 16; o > 0; o >>= 1)
                s += __shfl_xor_sync(0xffffffffu, s, o);
            float iv = 1.0f / s;
            if (lane == 0) inv[row] = iv;

            float sv = iv * 0.125f;
            float4* out4 = reinterpret_cast<float4*>(
                attn_out + mrow0 + (size_t)row * S_);
#pragma unroll
            for (int u8 = 0; u8 < 8; u8++) {
                int u = lane + 32 * u8;
                float4 ev = pr[u];
                float4 o;
                if (h == 0) {
                    o.x = ev.x * sv; o.y = ev.y * sv;
                    o.z = ev.z * sv; o.w = ev.w * sv;
                } else {
                    float4 ov = out4[u];
                    o.x = fmaf(ev.x, sv, ov.x);
                    o.y = fmaf(ev.y, sv, ov.y);
                    o.z = fmaf(ev.z, sv, ov.z);
                    o.w = fmaf(ev.w, sv, ov.w);
                }
                out4[u] = o;
            }
        }
        __syncthreads();

        // ================= PV phase (no tile barriers) =================
        // warp: cols nc*8..+7, s range [sh*256, sh*256+256), rows all 32
        float cv[2][4] = {{0,0,0,0},{0,0,0,0}};
        const size_t vbase = ((size_t)(b * 128) * 8 + h) * 256 +
                             (nc * 8 + gid) * 8 + tid4 * 2;
#pragma unroll 4
        for (int kstep = 0; kstep < 32; kstep++) {
            int sblk = sh * 32 + kstep;
            uint2 bvv = *reinterpret_cast<const uint2*>(
                &g_vh[vbase + (size_t)sblk * 2048]);
            unsigned bfrag[2] = {bvv.x, bvv.y};
            int s8 = sh * 256 + kstep * 8;
#pragma unroll
            for (int rt = 0; rt < 2; rt++) {
                unsigned av[4];
                av[0] = cvt_tf32(score[(rt*16 + gid) * SC_STR + s8 + tid4]);
                av[1] = cvt_tf32(score[(rt*16 + gid + 8) * SC_STR + s8 + tid4]);
                av[2] = cvt_tf32(score[(rt*16 + gid) * SC_STR + s8 + tid4 + 4]);
                av[3] = cvt_tf32(score[(rt*16 + gid + 8) * SC_STR + s8 + tid4 + 4]);
                mma_tf32(cv[rt], av, bfrag);
            }
        }

        // partials -> red[sh]
#pragma unroll
        for (int rt = 0; rt < 2; rt++)
#pragma unroll
            for (int rp = 0; rp < 2; rp++) {
                int row = rt * 16 + gid + 8 * rp;
                *reinterpret_cast<float2*>(
                    &red[sh * 1152 + row * 36 + nc * 8 + 2 * tid4]) =
                    make_float2(cv[rt][2*rp], cv[rt][2*rp+1]);
            }
        __syncthreads();

        // combine quarters + normalize + write ctx
#pragma unroll
        for (int u = 0; u < 2; u++) {
            int e = t + 512 * u;                   // 0..1023
            int row = e >> 5, d = e & 31;
            float s = red[row * 36 + d] + red[1152 + row * 36 + d] +
                      red[2304 + row * 36 + d] + red[3456 + row * 36 + d];
            g_ctx[(qbase + row) * V_ + h * 32 + d] = s * inv[row];
        }
    }
}

// ---------------------------------------------------------------------------
extern "C" void kernel_launch(void* const* d_in, const int* in_sizes, int n_in,
                              void* d_out, int out_size)
{
    const float* q    = (const float*)d_in[0];
    const float* k    = (const float*)d_in[1];
    const float* v    = (const float*)d_in[2];
    const int*   qid  = (const int*)d_in[3];
    const int*   kid  = (const int*)d_in[4];
    const float* mask = (const float*)d_in[5];
    const float* wqs  = (const float*)d_in[6];
    const float* wqo  = (const float*)d_in[7];
    const float* wks  = (const float*)d_in[8];
    const float* wko  = (const float*)d_in[9];
    const float* wv   = (const float*)d_in[10];
    const float* fcw  = (const float*)d_in[11];
    const float* fcb  = (const float*)d_in[12];

    float* out      = (float*)d_out;
    float* attn_out = out + (size_t)B_ * L_ * V_;

    void *p_qs, *p_qo, *p_ks, *p_ko, *p_vh, *p_ctx;
    cudaGetSymbolAddress(&p_qs,  g_qs);
    cudaGetSymbolAddress(&p_qo,  g_qo);
    cudaGetSymbolAddress(&p_ks,  g_ks);
    cudaGetSymbolAddress(&p_ko,  g_ko);
    cudaGetSymbolAddress(&p_vh,  g_vh);
    cudaGetSymbolAddress(&p_ctx, g_ctx);

    cudaFuncSetAttribute(attn_kernel,
                         cudaFuncAttributeMaxDynamicSharedMemorySize,
                         AT_SMEM_BYTES);

    Proj5 p;
    p.A[0] = q;  p.W[0] = wqs; p.C[0] = (float*)p_qs; p.sc[0] = SCALE_F; p.md[0] = 1;
    p.A[1] = q;  p.W[1] = wqo; p.C[1] = (float*)p_qo; p.sc[1] = SCALE_F; p.md[1] = 1;
    p.A[2] = k;  p.W[2] = wks; p.C[2] = (float*)p_ks; p.sc[2] = 1.0f;    p.md[2] = 1;
    p.A[3] = k;  p.W[3] = wko; p.C[3] = (float*)p_ko; p.sc[3] = 1.0f;    p.md[3] = 1;
    p.A[4] = v;  p.W[4] = wv;  p.C[4] = (float*)p_vh; p.sc[4] = 1.0f;    p.md[4] = 2;

    dim3 pgrid(V_ / 64, N_TOK / 128, 5);
    proj_kernel<<<pgrid, 256>>>(p);

    dim3 agrid(L_ / 32, B_);
    attn_kernel<<<agrid, 512, AT_SMEM_BYTES>>>(mask, qid, kid, attn_out);

    dim3 fgrid(V_ / 64, N_TOK / 128);
    fc_kernel<<<fgrid, 256>>>((const float*)p_ctx, fcw, fcb, out);
}

// round 8
// speedup vs baseline: 3.6359x; 1.0021x over previous
#include <cuda_runtime.h>
#include <math_constants.h>

#define B_  8
#define L_  1024
#define S_  1024
#define D_  256
#define V_  256
#define H_  8

#define N_TOK (B_*L_)
#define SCALE_F 0.17677669529663687f

// ---------------- scratch (static device arrays: allocation-free) ----------
// g_qs/g_qo/g_ks/g_ko: tf32 bits, row-major tokens, d-permuted so (d,d+4)
//   are adjacent:  pos = h*32 + 2*p + hi,  p = (dd>>3)*4 + (dd&3), hi=(dd>>2)&1
// g_vh: tf32 bits, blocked [b][sblk=s/8][h][col=32][8] with (s, s+4) adjacent
__device__ float g_qs[N_TOK*D_];
__device__ float g_qo[N_TOK*D_];
__device__ float g_ks[N_TOK*D_];
__device__ float g_ko[N_TOK*D_];
__device__ float g_vh[N_TOK*D_];
__device__ float g_ctx[N_TOK*V_];

// ---------------- fast exp on FMA pipe (rel err ~2e-6) ---------------------
__device__ __forceinline__ float fexp(float x)
{
    float t = fmaxf(x * 1.4426950408889634f, -125.0f);
    float r = rintf(t);
    float f = t - r;
    float p = 1.3333558146428443e-3f;
    p = fmaf(p, f, 9.6181291076284772e-3f);
    p = fmaf(p, f, 5.5504108664821580e-2f);
    p = fmaf(p, f, 2.4022650695910071e-1f);
    p = fmaf(p, f, 6.9314718055994531e-1f);
    p = fmaf(p, f, 1.0f);
    return __int_as_float(__float_as_int(p) + (((int)r) << 23));
}

// ---------------- tf32 mma helpers -----------------------------------------
__device__ __forceinline__ unsigned cvt_tf32(float f)
{
    unsigned r;
    asm("cvt.rna.tf32.f32 %0, %1;" : "=r"(r) : "f"(f));
    return r;
}

__device__ __forceinline__ void mma_tf32(float c[4], const unsigned a[4],
                                         const unsigned b[2])
{
    asm("mma.sync.aligned.m16n8k8.row.col.f32.tf32.tf32.f32 "
        "{%0,%1,%2,%3}, {%4,%5,%6,%7}, {%8,%9}, {%0,%1,%2,%3};"
        : "+f"(c[0]), "+f"(c[1]), "+f"(c[2]), "+f"(c[3])
        : "r"(a[0]), "r"(a[1]), "r"(a[2]), "r"(a[3]),
          "r"(b[0]), "r"(b[1]));
}

// ---------------------------------------------------------------------------
// GEMM (fp32, 8x8 thread tile, reg prefetch): C = scale*(A @ Bw^T) + bias.
// BM=128, BN=128, BK=16, 256 threads. Thread cols: tx*4 and 64+tx*4.
// mode 0: plain fp32 row-major (+bias)
// mode 1: tf32, d-pair permuted row-major (q/k scratch)
// mode 2: tf32, s-pair blocked layout (v scratch)
// ---------------------------------------------------------------------------
__device__ __forceinline__ void gemm_body(
    const float* __restrict__ A, const float* __restrict__ Bw,
    float* __restrict__ C, int N, int K,
    float scale, const float* __restrict__ bias, int mode)
{
    const int BM = 128, BN = 128, BK = 16;
    __shared__ __align__(16) float As[BK][BM + 4];
    __shared__ __align__(16) float Bs[BK][BN + 4];

    int t  = threadIdx.x;
    int m0 = blockIdx.y * BM;
    int n0 = blockIdx.x * BN;
    int tx = t & 15;
    int ty = t >> 4;

    float acc[8][8];
#pragma unroll
    for (int i = 0; i < 8; i++)
#pragma unroll
        for (int j = 0; j < 8; j++) acc[i][j] = 0.f;

    const int ra = t >> 2;            // 0..63
    const int ca = (t & 3) * 4;       // 0,4,8,12

    float4 pa0 = *reinterpret_cast<const float4*>(&A[(size_t)(m0 + ra) * K + ca]);
    float4 pa1 = *reinterpret_cast<const float4*>(&A[(size_t)(m0 + ra + 64) * K + ca]);
    float4 pb0 = *reinterpret_cast<const float4*>(&Bw[(size_t)(n0 + ra) * K + ca]);
    float4 pb1 = *reinterpret_cast<const float4*>(&Bw[(size_t)(n0 + ra + 64) * K + ca]);

    for (int k0 = 0; k0 < K; k0 += BK) {
        As[ca + 0][ra] = pa0.x;  As[ca + 1][ra] = pa0.y;
        As[ca + 2][ra] = pa0.z;  As[ca + 3][ra] = pa0.w;
        As[ca + 0][ra + 64] = pa1.x;  As[ca + 1][ra + 64] = pa1.y;
        As[ca + 2][ra + 64] = pa1.z;  As[ca + 3][ra + 64] = pa1.w;
        Bs[ca + 0][ra] = pb0.x;  Bs[ca + 1][ra] = pb0.y;
        Bs[ca + 2][ra] = pb0.z;  Bs[ca + 3][ra] = pb0.w;
        Bs[ca + 0][ra + 64] = pb1.x;  Bs[ca + 1][ra + 64] = pb1.y;
        Bs[ca + 2][ra + 64] = pb1.z;  Bs[ca + 3][ra + 64] = pb1.w;
        __syncthreads();

        if (k0 + BK < K) {
            int c = k0 + BK + ca;
            pa0 = *reinterpret_cast<const float4*>(&A[(size_t)(m0 + ra) * K + c]);
            pa1 = *reinterpret_cast<const float4*>(&A[(size_t)(m0 + ra + 64) * K + c]);
            pb0 = *reinterpret_cast<const float4*>(&Bw[(size_t)(n0 + ra) * K + c]);
            pb1 = *reinterpret_cast<const float4*>(&Bw[(size_t)(n0 + ra + 64) * K + c]);
        }

#pragma unroll
        for (int k = 0; k < BK; k++) {
            float4 a0 = *reinterpret_cast<const float4*>(&As[k][ty * 8]);
            float4 a1 = *reinterpret_cast<const float4*>(&As[k][ty * 8 + 4]);
            float4 b0 = *reinterpret_cast<const float4*>(&Bs[k][tx * 4]);
            float4 b1 = *reinterpret_cast<const float4*>(&Bs[k][tx * 4 + 64]);
            float a[8] = {a0.x, a0.y, a0.z, a0.w, a1.x, a1.y, a1.z, a1.w};
            float bb[8] = {b0.x, b0.y, b0.z, b0.w, b1.x, b1.y, b1.z, b1.w};
#pragma unroll
            for (int i = 0; i < 8; i++)
#pragma unroll
                for (int j = 0; j < 8; j++) acc[i][j] += a[i] * bb[j];
        }
        __syncthreads();
    }

    if (mode == 0) {
        float bv[8];
#pragma unroll
        for (int j = 0; j < 8; j++) bv[j] = 0.f;
        if (bias) {
#pragma unroll
            for (int j = 0; j < 4; j++) {
                bv[j]     = bias[n0 + tx * 4 + j];
                bv[j + 4] = bias[n0 + 64 + tx * 4 + j];
            }
        }
#pragma unroll
        for (int i = 0; i < 8; i++) {
            int row = m0 + ty * 8 + i;
            float4 o0, o1;
            o0.x = acc[i][0] * scale + bv[0];
            o0.y = acc[i][1] * scale + bv[1];
            o0.z = acc[i][2] * scale + bv[2];
            o0.w = acc[i][3] * scale + bv[3];
            o1.x = acc[i][4] * scale + bv[4];
            o1.y = acc[i][5] * scale + bv[5];
            o1.z = acc[i][6] * scale + bv[6];
            o1.w = acc[i][7] * scale + bv[7];
            *reinterpret_cast<float4*>(&C[(size_t)row * N + n0 + tx * 4]) = o0;
            *reinterpret_cast<float4*>(&C[(size_t)row * N + n0 + 64 + tx * 4]) = o1;
        }
    } else if (mode == 1) {
        // tf32, d-pair permuted row-major
#pragma unroll
        for (int i = 0; i < 8; i++) {
            int row = m0 + ty * 8 + i;
#pragma unroll
            for (int j = 0; j < 8; j++) {
                int n  = n0 + ((j < 4) ? (tx * 4 + j) : (64 + tx * 4 + j - 4));
                int hh = n >> 5, dd = n & 31;
                int p  = ((dd >> 3) << 2) | (dd & 3);
                int pos = (hh << 5) + 2 * p + ((dd >> 2) & 1);
                C[(size_t)row * D_ + pos] =
                    __uint_as_float(cvt_tf32(acc[i][j] * scale));
            }
        }
    } else {
        // tf32, v blocked layout: [b][sblk][h][col][8], (s, s+4) adjacent
#pragma unroll
        for (int i = 0; i < 4; i++) {
            int row  = m0 + ty * 8 + i;
            int bb2  = row >> 10;
            int s    = row & 1023;
            int sblk = s >> 3;
#pragma unroll
            for (int j = 0; j < 8; j++) {
                int n  = n0 + ((j < 4) ? (tx * 4 + j) : (64 + tx * 4 + j - 4));
                int hh = n >> 5, col = n & 31;
                size_t idx = (((size_t)(bb2 * 128 + sblk) * 8 + hh)) * 256 +
                             col * 8 + i * 2;
                float2 o;
                o.x = __uint_as_float(cvt_tf32(acc[i][j]));
                o.y = __uint_as_float(cvt_tf32(acc[i + 4][j]));
                *reinterpret_cast<float2*>(&C[idx]) = o;
            }
        }
    }
}

struct Proj5 {
    const float* A[5];
    const float* W[5];
    float*       C[5];
    float        sc[5];
    int          md[5];
};

__global__ __launch_bounds__(256, 2)
void proj_kernel(Proj5 p)
{
    int z = blockIdx.z;
    gemm_body(p.A[z], p.W[z], p.C[z], D_, D_, p.sc[z], nullptr, p.md[z]);
}

__global__ __launch_bounds__(256, 2)
void fc_kernel(const float* __restrict__ A, const float* __restrict__ W,
               const float* __restrict__ bias, float* __restrict__ C)
{
    gemm_body(A, W, C, V_, V_, 1.0f, bias, 0);
}

// ---------------------------------------------------------------------------
// Attention (tf32 mma, barrier-light): block = (b, 32 l-rows), 512 thr, 1/SM.
// All MMA operands (q,k,v) stream as LDG.64 fragments from L2-resident,
// pre-permuted tf32 scratch. 4 barriers per head.
// smem floats: score [32][1036] | red [4][32][36] | inv 32 | qid 32 | kid 1024
// ---------------------------------------------------------------------------
#define SC_STR 1036
#define AT_SMEM_BYTES ((32*SC_STR + 4608 + 32 + 32 + 1024) * 4)

__global__ __launch_bounds__(512, 1)
void attn_kernel(const float* __restrict__ mask,
                 const int* __restrict__ qid,
                 const int* __restrict__ kid,
                 float* __restrict__ attn_out)
{
    extern __shared__ float sm[];
    float* score = sm;                        // [32][1036]
    float* red   = sm + 32 * SC_STR;          // [4][32][36]
    float* inv   = red + 4608;                // [32]
    int*   qid_s = (int*)(inv + 32);          // [32]
    int*   kid_s = qid_s + 32;                // [1024]

    const int b    = blockIdx.y;
    const int l0   = blockIdx.x * 32;
    const int t    = threadIdx.x;
    const int lane = t & 31;
    const int w    = t >> 5;                  // 0..15
    const int gid  = lane >> 2;
    const int tid4 = lane & 3;

    const size_t qbase = (size_t)(b * L_ + l0);
    const size_t kbase = (size_t)(b * S_);
    const size_t mrow0 = qbase * S_;

    // score-phase: warp w owns cols w*64 .. w*64+63, all 32 rows
    const int cb = w * 64;
    // PV: warp = (nc, sh): cols nc*8, s-quarter sh*256
    const int nc = w & 3;
    const int sh = w >> 2;

    for (int i = t; i < S_; i += 512) kid_s[i] = kid[b * S_ + i];
    if (t < 32) qid_s[t] = qid[b * L_ + l0 + t];

    for (int h = 0; h < H_; h++) {
        __syncthreads();   // prev head fully done; ids visible (h=0)

        // ---- A fragments (q self/other): LDG.64 pairs, already tf32 ----
        unsigned aS[2][4][4], aO[2][4][4];
#pragma unroll
        for (int rt = 0; rt < 2; rt++) {
            const size_t r0 = (qbase + rt * 16 + gid) * D_ + h * 32;
            const size_t r1 = (qbase + rt * 16 + gid + 8) * D_ + h * 32;
#pragma unroll
            for (int ks = 0; ks < 4; ks++) {
                int off = 2 * (ks * 4 + tid4);
                uint2 lo = *reinterpret_cast<const uint2*>(&g_qs[r0 + off]);
                uint2 hi = *reinterpret_cast<const uint2*>(&g_qs[r1 + off]);
                aS[rt][ks][0] = lo.x; aS[rt][ks][1] = hi.x;
                aS[rt][ks][2] = lo.y; aS[rt][ks][3] = hi.y;
                lo = *reinterpret_cast<const uint2*>(&g_qo[r0 + off]);
                hi = *reinterpret_cast<const uint2*>(&g_qo[r1 + off]);
                aO[rt][ks][0] = lo.x; aO[rt][ks][1] = hi.x;
                aO[rt][ks][2] = lo.y; aO[rt][ks][3] = hi.y;
            }
        }

        int qi[2][2];
#pragma unroll
        for (int rt = 0; rt < 2; rt++) {
            qi[rt][0] = qid_s[rt * 16 + gid];
            qi[rt][1] = qid_s[rt * 16 + gid + 8];
        }

        // ================= score phase (no barriers) =================
#pragma unroll 2
        for (int nt = 0; nt < 8; nt++) {
            const int sK   = cb + nt * 8 + gid;
            const int scol = cb + nt * 8 + 2 * tid4;

            unsigned bS[4][2], bO[4][2];
            const size_t krow = (kbase + sK) * D_ + h * 32;
#pragma unroll
            for (int ks = 0; ks < 4; ks++) {
                int off = 2 * (ks * 4 + tid4);
                uint2 v = *reinterpret_cast<const uint2*>(&g_ks[krow + off]);
                bS[ks][0] = v.x; bS[ks][1] = v.y;
                v = *reinterpret_cast<const uint2*>(&g_ko[krow + off]);
                bO[ks][0] = v.x; bO[ks][1] = v.y;
            }

            int2 ki = *reinterpret_cast<const int2*>(&kid_s[scol]);
            float2 mf[2][2];
#pragma unroll
            for (int rt = 0; rt < 2; rt++)
#pragma unroll
                for (int rp = 0; rp < 2; rp++) {
                    int row = rt * 16 + gid + 8 * rp;
                    mf[rt][rp] = *reinterpret_cast<const float2*>(
                        &mask[mrow0 + (size_t)row * S_ + scol]);
                }

            float cS[2][4] = {{0,0,0,0},{0,0,0,0}};
            float cO[2][4] = {{0,0,0,0},{0,0,0,0}};
#pragma unroll
            for (int ks = 0; ks < 4; ks++) {
#pragma unroll
                for (int rt = 0; rt < 2; rt++) {
                    mma_tf32(cS[rt], aS[rt][ks], bS[ks]);
                    mma_tf32(cO[rt], aO[rt][ks], bO[ks]);
                }
            }

#pragma unroll
            for (int rt = 0; rt < 2; rt++)
#pragma unroll
                for (int rp = 0; rp < 2; rp++) {
                    int row = rt * 16 + gid + 8 * rp;
                    float v0 = ((qi[rt][rp] == ki.x) ? cS[rt][2*rp]   : cO[rt][2*rp])   + mf[rt][rp].x;
                    float v1 = ((qi[rt][rp] == ki.y) ? cS[rt][2*rp+1] : cO[rt][2*rp+1]) + mf[rt][rp].y;
                    *reinterpret_cast<float2*>(&score[row * SC_STR + scol]) =
                        make_float2(v0, v1);
                }
        }
        __syncthreads();

        // ======= softmax + folded attn-sum (warp w: rows 2w, 2w+1) =========
        // attn-sum pass also rounds e-values to tf32 bits in-place for PV.
#pragma unroll
        for (int rr = 0; rr < 2; rr++) {
            int row = 2 * w + rr;
            float4* pr = (float4*)(score + row * SC_STR);
            float mx = -CUDART_INF_F;
#pragma unroll
            for (int u8 = 0; u8 < 8; u8++) {
                float4 x = pr[lane + 32 * u8];
                mx = fmaxf(mx, fmaxf(fmaxf(x.x, x.y), fmaxf(x.z, x.w)));
            }
#pragma unroll
            for (int o = 16; o > 0; o >>= 1)
                mx = fmaxf(mx, __shfl_xor_sync(0xffffffffu, mx, o));
            float s = 0.f;
#pragma unroll
            for (int u8 = 0; u8 < 8; u8++) {
                float4 x = pr[lane + 32 * u8];
                x.x = fexp(x.x - mx); x.y = fexp(x.y - mx);
                x.z = fexp(x.z - mx); x.w = fexp(x.w - mx);
                s += (x.x + x.y) + (x.z + x.w);
                pr[lane + 32 * u8] = x;
            }
#pragma unroll
            for (int o = 16; o > 0; o >>= 1)
                s += __shfl_xor_sync(0xffffffffu, s, o);
            float iv = 1.0f / s;
            if (lane == 0) inv[row] = iv;

            float sv = iv * 0.125f;
            float4* out4 = reinterpret_cast<float4*>(
                attn_out + mrow0 + (size_t)row * S_);
#pragma unroll
            for (int u8 = 0; u8 < 8; u8++) {
                int u = lane + 32 * u8;
                float4 ev = pr[u];
                float4 o;
                if (h == 0) {
                    o.x = ev.x * sv; o.y = ev.y * sv;
                    o.z = ev.z * sv; o.w = ev.w * sv;
                } else {
                    float4 ov = out4[u];
                    o.x = fmaf(ev.x, sv, ov.x);
                    o.y = fmaf(ev.y, sv, ov.y);
                    o.z = fmaf(ev.z, sv, ov.z);
                    o.w = fmaf(ev.w, sv, ov.w);
                }
                out4[u] = o;
                // write back tf32-rounded e-values for the PV mma
                float4 rv;
                rv.x = __uint_as_float(cvt_tf32(ev.x));
                rv.y = __uint_as_float(cvt_tf32(ev.y));
                rv.z = __uint_as_float(cvt_tf32(ev.z));
                rv.w = __uint_as_float(cvt_tf32(ev.w));
                pr[u] = rv;
            }
        }
        __syncthreads();

        // ================= PV phase (no tile barriers) =================
        float cv[2][4] = {{0,0,0,0},{0,0,0,0}};
        const size_t vbase = ((size_t)(b * 128) * 8 + h) * 256 +
                             (nc * 8 + gid) * 8 + tid4 * 2;
#pragma unroll 4
        for (int kstep = 0; kstep < 32; kstep++) {
            int sblk = sh * 32 + kstep;
            uint2 bvv = *reinterpret_cast<const uint2*>(
                &g_vh[vbase + (size_t)sblk * 2048]);
            unsigned bfrag[2] = {bvv.x, bvv.y};
            int s8 = sh * 256 + kstep * 8;
#pragma unroll
            for (int rt = 0; rt < 2; rt++) {
                unsigned av[4];
                av[0] = __float_as_uint(score[(rt*16 + gid) * SC_STR + s8 + tid4]);
                av[1] = __float_as_uint(score[(rt*16 + gid + 8) * SC_STR + s8 + tid4]);
                av[2] = __float_as_uint(score[(rt*16 + gid) * SC_STR + s8 + tid4 + 4]);
                av[3] = __float_as_uint(score[(rt*16 + gid + 8) * SC_STR + s8 + tid4 + 4]);
                mma_tf32(cv[rt], av, bfrag);
            }
        }

        // partials -> red[sh]
#pragma unroll
        for (int rt = 0; rt < 2; rt++)
#pragma unroll
            for (int rp = 0; rp < 2; rp++) {
                int row = rt * 16 + gid + 8 * rp;
                *reinterpret_cast<float2*>(
                    &red[sh * 1152 + row * 36 + nc * 8 + 2 * tid4]) =
                    make_float2(cv[rt][2*rp], cv[rt][2*rp+1]);
            }
        __syncthreads();

        // combine quarters + normalize + write ctx
#pragma unroll
        for (int u = 0; u < 2; u++) {
            int e = t + 512 * u;                   // 0..1023
            int row = e >> 5, d = e & 31;
            float s = red[row * 36 + d] + red[1152 + row * 36 + d] +
                      red[2304 + row * 36 + d] + red[3456 + row * 36 + d];
            g_ctx[(qbase + row) * V_ + h * 32 + d] = s * inv[row];
        }
    }
}

// ---------------------------------------------------------------------------
extern "C" void kernel_launch(void* const* d_in, const int* in_sizes, int n_in,
                              void* d_out, int out_size)
{
    const float* q    = (const float*)d_in[0];
    const float* k    = (const float*)d_in[1];
    const float* v    = (const float*)d_in[2];
    const int*   qid  = (const int*)d_in[3];
    const int*   kid  = (const int*)d_in[4];
    const float* mask = (const float*)d_in[5];
    const float* wqs  = (const float*)d_in[6];
    const float* wqo  = (const float*)d_in[7];
    const float* wks  = (const float*)d_in[8];
    const float* wko  = (const float*)d_in[9];
    const float* wv   = (const float*)d_in[10];
    const float* fcw  = (const float*)d_in[11];
    const float* fcb  = (const float*)d_in[12];

    float* out      = (float*)d_out;
    float* attn_out = out + (size_t)B_ * L_ * V_;

    void *p_qs, *p_qo, *p_ks, *p_ko, *p_vh, *p_ctx;
    cudaGetSymbolAddress(&p_qs,  g_qs);
    cudaGetSymbolAddress(&p_qo,  g_qo);
    cudaGetSymbolAddress(&p_ks,  g_ks);
    cudaGetSymbolAddress(&p_ko,  g_ko);
    cudaGetSymbolAddress(&p_vh,  g_vh);
    cudaGetSymbolAddress(&p_ctx, g_ctx);

    cudaFuncSetAttribute(attn_kernel,
                         cudaFuncAttributeMaxDynamicSharedMemorySize,
                         AT_SMEM_BYTES);

    Proj5 p;
    p.A[0] = q;  p.W[0] = wqs; p.C[0] = (float*)p_qs; p.sc[0] = SCALE_F; p.md[0] = 1;
    p.A[1] = q;  p.W[1] = wqo; p.C[1] = (float*)p_qo; p.sc[1] = SCALE_F; p.md[1] = 1;
    p.A[2] = k;  p.W[2] = wks; p.C[2] = (float*)p_ks; p.sc[2] = 1.0f;    p.md[2] = 1;
    p.A[3] = k;  p.W[3] = wko; p.C[3] = (float*)p_ko; p.sc[3] = 1.0f;    p.md[3] = 1;
    p.A[4] = v;  p.W[4] = wv;  p.C[4] = (float*)p_vh; p.sc[4] = 1.0f;    p.md[4] = 2;

    dim3 pgrid(V_ / 128, N_TOK / 128, 5);   // (2, 64, 5)
    proj_kernel<<<pgrid, 256>>>(p);

    dim3 agrid(L_ / 32, B_);
    attn_kernel<<<agrid, 512, AT_SMEM_BYTES>>>(mask, qid, kid, attn_out);

    dim3 fgrid(V_ / 128, N_TOK / 128);      // (2, 64)
    fc_kernel<<<fgrid, 256>>>((const float*)p_ctx, fcw, fcb, out);
}